// round 14
// baseline (speedup 1.0000x reference)
#include <cuda_runtime.h>
#include <cuda_fp16.h>
#include <cstdint>

#define Bq 64
#define Hq 1024
#define NG 4096
#define DIN 768
#define TAUD 500
#define Lq 127
#define SEQLEN 128
#define NPB 128       // 4 groups x 32 blocks (champion shape)

// ---- dynamic smem (bytes), KC=128 ----
// X bufs: 2 x 64 rows x 272B  = 34816
// W bufs: 2 x 128 rows x 272B = 69632
// GS: 64 x 130 f32 = 33280
#define SM_W 34816
#define SM_GS 104448
#define SMEM_BYTES 137728

// -------- scratch --------
__device__ float g_pooled[Bq * DIN];
__device__ __half g_enc16[Bq * Hq];
__device__ float g_WT[Hq * NG];                 // Wih0^T: [char][gate-row]
__device__ __half g_Wpk[4u * 32u * 128u * 1024u];  // 4 sets x 32 slices x 128 rows
__device__ __half g_Wout16[Hq * Hq];
__device__ __half g_h0h[(size_t)Lq * Bq * Hq];  // h0 full history
__device__ __half g_outs16[(size_t)Lq * Bq * Hq];  // h1 history == outputs
__device__ float g_pih[2][Bq * NG];             // layer1 partial ih gates
__device__ int g_fh0[Lq][4];
__device__ int g_fpih[Lq][4];
__device__ int g_fh1[Lq][4];

__device__ __forceinline__ float sigf(float x) { return 1.0f / (1.0f + __expf(-x)); }

__device__ __forceinline__ uint32_t h2_as_u32(__half2 h) {
    return *reinterpret_cast<uint32_t*>(&h);
}

__device__ __forceinline__ uint32_t s2u(const void* p) {
    uint32_t a;
    asm("{ .reg .u64 t; cvta.to.shared.u64 t, %1; cvt.u32.u64 %0, t; }" : "=r"(a) : "l"(p));
    return a;
}

__device__ __forceinline__ uint32_t f2tf32(float f) {
    uint32_t u;
    asm("cvt.rna.tf32.f32 %0, %1;" : "=r"(u) : "f"(f));
    return u;
}

__device__ __forceinline__ void ldsm_x4(uint32_t& r0, uint32_t& r1, uint32_t& r2, uint32_t& r3,
                                        uint32_t addr) {
    asm volatile("ldmatrix.sync.aligned.m8n8.x4.shared.b16 {%0,%1,%2,%3}, [%4];"
                 : "=r"(r0), "=r"(r1), "=r"(r2), "=r"(r3) : "r"(addr));
}
__device__ __forceinline__ void ldsm_x2(uint32_t& r0, uint32_t& r1, uint32_t addr) {
    asm volatile("ldmatrix.sync.aligned.m8n8.x2.shared.b16 {%0,%1}, [%2];"
                 : "=r"(r0), "=r"(r1) : "r"(addr));
}

__device__ __forceinline__ void mma16816h(uint32_t& d0, uint32_t& d1,
                                          uint32_t a0, uint32_t a1, uint32_t a2, uint32_t a3,
                                          uint32_t b0, uint32_t b1) {
    asm volatile("mma.sync.aligned.m16n8k16.row.col.f16.f16.f16.f16 "
                 "{%0,%1}, {%2,%3,%4,%5}, {%6,%7}, {%0,%1};"
                 : "+r"(d0), "+r"(d1)
                 : "r"(a0), "r"(a1), "r"(a2), "r"(a3), "r"(b0), "r"(b1));
}

__device__ __forceinline__ void promo4(float* a4, uint32_t h0, uint32_t h1) {
    float2 lo = __half22float2(*reinterpret_cast<__half2*>(&h0));
    float2 hi = __half22float2(*reinterpret_cast<__half2*>(&h1));
    a4[0] += lo.x; a4[1] += lo.y; a4[2] += hi.x; a4[3] += hi.y;
}

__device__ __forceinline__ void mma_tf32(float& c0, float& c1, float& c2, float& c3,
                                         uint32_t a0, uint32_t a1, uint32_t a2, uint32_t a3,
                                         uint32_t b0, uint32_t b1) {
    asm volatile("mma.sync.aligned.m16n8k8.row.col.f32.tf32.tf32.f32 "
                 "{%0,%1,%2,%3}, {%4,%5,%6,%7}, {%8,%9}, {%0,%1,%2,%3};"
                 : "+f"(c0), "+f"(c1), "+f"(c2), "+f"(c3)
                 : "r"(a0), "r"(a1), "r"(a2), "r"(a3), "r"(b0), "r"(b1));
}

// wait until 4 sub-counters sum to 256 (all 8 warps of all 32 producer blocks)
__device__ __forceinline__ void waitf(const int* f) {
    int s;
    do {
        int a, b, c, d;
        asm volatile("ld.acquire.gpu.s32 %0,[%1];" : "=r"(a) : "l"(f));
        asm volatile("ld.acquire.gpu.s32 %0,[%1];" : "=r"(b) : "l"(f + 1));
        asm volatile("ld.acquire.gpu.s32 %0,[%1];" : "=r"(c) : "l"(f + 2));
        asm volatile("ld.acquire.gpu.s32 %0,[%1];" : "=r"(d) : "l"(f + 3));
        s = a + b + c + d;
    } while (s < 256);
}

__global__ void reset_kernel() {
    int i = blockIdx.x * blockDim.x + threadIdx.x;
    if (i < Lq * 4) {
        ((int*)g_fh0)[i] = 0;
        ((int*)g_fpih)[i] = 0;
        ((int*)g_fh1)[i] = 0;
    }
}

// -------- mean-pool audio --------
__global__ void pool_kernel(const float* __restrict__ audio) {
    int i = blockIdx.x * blockDim.x + threadIdx.x;
    int b = i / DIN, d = i % DIN;
    const float* p = audio + (size_t)b * TAUD * DIN + d;
    float s = 0.f;
#pragma unroll 5
    for (int t = 0; t < TAUD; t++) s += __ldcs(p + (size_t)t * DIN);
    g_pooled[i] = s * (1.0f / TAUD);
}

// -------- transpose Wih0 -> WT[char][gate-row] --------
__global__ void transpose_kernel(const float* __restrict__ W) {
    __shared__ float tile[32][33];
    int bx = blockIdx.x, by = blockIdx.y;
    int tx = threadIdx.x, ty0 = threadIdx.y;
#pragma unroll
    for (int q = 0; q < 4; q++) {
        int ty = ty0 + q * 8;
        tile[ty][tx] = W[(size_t)(by * 32 + ty) * Hq + bx * 32 + tx];
    }
    __syncthreads();
#pragma unroll
    for (int q = 0; q < 4; q++) {
        int ty = ty0 + q * 8;
        g_WT[(size_t)(bx * 32 + ty) * NG + by * 32 + tx] = tile[tx][ty];
    }
}

// -------- pack fp16 W slices: 4 sets x 32 slices x 128 rows (32u x 4g) --------
// sets: 0=Whh0, 1=Whh1, 2=Wih1, 3=Wih0;  row r: gate=r>>5, unit=j0+(r&31)
__global__ void pack_w16_kernel(const float* __restrict__ W0,
                                const float* __restrict__ W1,
                                const float* __restrict__ W2,
                                const float* __restrict__ W3) {
    int id = blockIdx.x;              // 0..511
    int grp = id >> 7;
    int rem = id & 127;
    int blk = rem >> 2;
    int qtr = rem & 3;
    const float* W = (grp == 0) ? W0 : (grp == 1 ? W1 : (grp == 2 ? W2 : W3));
    int j0 = blk * 32;
    __half* dst = g_Wpk + ((size_t)(grp * 32 + blk)) * 131072;
    int f4e = (qtr + 1) * 8192;
    for (int f4 = qtr * 8192 + threadIdx.x; f4 < f4e; f4 += 256) {
        int r = f4 >> 8;
        int c = (f4 & 255) * 4;
        int grow = (r >> 5) * Hq + j0 + (r & 31);
        float4 v = *(const float4*)(W + (size_t)grow * Hq + c);
        uint2 o;
        o.x = h2_as_u32(__floats2half2_rn(v.x, v.y));
        o.y = h2_as_u32(__floats2half2_rn(v.z, v.w));
        *(uint2*)(dst + (size_t)r * 1024 + c) = o;
    }
}

// -------- pack W_out to fp16 row-major --------
__global__ void pack_wout_kernel(const float* __restrict__ W) {
    int i = blockIdx.x * blockDim.x + threadIdx.x;
    float4 v = *(const float4*)(W + (size_t)i * 4);
    uint2 o;
    o.x = h2_as_u32(__floats2half2_rn(v.x, v.y));
    o.y = h2_as_u32(__floats2half2_rn(v.z, v.w));
    *(uint2*)(g_Wout16 + (size_t)i * 4) = o;
}

// ============ SIMT tf32 GEMM: enc = pooled @ W_proj^T + b -> fp16 ============
__global__ __launch_bounds__(256, 2)
void gemm_enc_kernel(const float* __restrict__ Bw,
                     const float* __restrict__ bias, int K) {
    __shared__ uint32_t As[64][36];
    __shared__ uint32_t Bs[64][36];
    const float* A = g_pooled;

    int tid = threadIdx.x;
    int lane = tid & 31, warp = tid >> 5;
    int nblk = blockIdx.x;
    int m0 = (warp & 3) * 16;
    int n0 = (warp >> 2) * 32;
    float acc[4][4] = {};
    int row = tid >> 3;
    int c4 = (tid & 7) * 4;

    const float* ap0 = A + (size_t)row * K + c4;
    const float* ap1 = A + (size_t)(row + 32) * K + c4;
    const float* bp0 = Bw + (size_t)(nblk * 64 + row) * K + c4;
    const float* bp1 = Bw + (size_t)(nblk * 64 + row + 32) * K + c4;

    int nC = K / 32;
    float4 xv0 = *(const float4*)ap0;
    float4 xv1 = *(const float4*)ap1;
    float4 wv0 = *(const float4*)bp0;
    float4 wv1 = *(const float4*)bp1;

    for (int c = 0; c < nC; c++) {
        uint4 u;
        u.x = f2tf32(xv0.x); u.y = f2tf32(xv0.y); u.z = f2tf32(xv0.z); u.w = f2tf32(xv0.w);
        *(uint4*)&As[row][c4] = u;
        u.x = f2tf32(xv1.x); u.y = f2tf32(xv1.y); u.z = f2tf32(xv1.z); u.w = f2tf32(xv1.w);
        *(uint4*)&As[row + 32][c4] = u;
        u.x = f2tf32(wv0.x); u.y = f2tf32(wv0.y); u.z = f2tf32(wv0.z); u.w = f2tf32(wv0.w);
        *(uint4*)&Bs[row][c4] = u;
        u.x = f2tf32(wv1.x); u.y = f2tf32(wv1.y); u.z = f2tf32(wv1.z); u.w = f2tf32(wv1.w);
        *(uint4*)&Bs[row + 32][c4] = u;
        __syncthreads();

        if (c + 1 < nC) {
            int k0 = (c + 1) * 32;
            xv0 = *(const float4*)(ap0 + k0);
            xv1 = *(const float4*)(ap1 + k0);
            wv0 = *(const float4*)(bp0 + k0);
            wv1 = *(const float4*)(bp1 + k0);
        }
#pragma unroll
        for (int ks = 0; ks < 4; ks++) {
            int kk = ks * 8;
            uint32_t a0 = As[m0 + (lane >> 2)][kk + (lane & 3)];
            uint32_t a1 = As[m0 + (lane >> 2) + 8][kk + (lane & 3)];
            uint32_t a2 = As[m0 + (lane >> 2)][kk + (lane & 3) + 4];
            uint32_t a3 = As[m0 + (lane >> 2) + 8][kk + (lane & 3) + 4];
#pragma unroll
            for (int nt = 0; nt < 4; nt++) {
                uint32_t b0 = Bs[n0 + nt * 8 + (lane >> 2)][kk + (lane & 3)];
                uint32_t b1 = Bs[n0 + nt * 8 + (lane >> 2)][kk + (lane & 3) + 4];
                mma_tf32(acc[nt][0], acc[nt][1], acc[nt][2], acc[nt][3],
                         a0, a1, a2, a3, b0, b1);
            }
        }
        __syncthreads();
    }

#pragma unroll
    for (int nt = 0; nt < 4; nt++) {
        int r = m0 + (lane >> 2);
        int cc = nblk * 64 + n0 + nt * 8 + (lane & 3) * 2;
        float bz0 = bias[cc], bz1 = bias[cc + 1];
        *(uint32_t*)&g_enc16[r * Hq + cc] =
            h2_as_u32(__floats2half2_rn(acc[nt][0] + bz0, acc[nt][1] + bz1));
        *(uint32_t*)&g_enc16[(r + 8) * Hq + cc] =
            h2_as_u32(__floats2half2_rn(acc[nt][2] + bz0, acc[nt][3] + bz1));
    }
}

// ============ persistent 4-group dataflow LSTM + logits (KC=128) ============
// grp0 [0,32):   h0(s)       grp1 [32,64): h1(s) = hh-GEMM + pih + epi
// grp2 [64,96):  pih(s)      grp3 [96,128): logits(s), N=32 cols
__global__ __launch_bounds__(256, 1)
void lstm_fp16_kernel(const float* __restrict__ bih0, const float* __restrict__ bhh0,
                      const float* __restrict__ bih1, const float* __restrict__ bhh1,
                      const float* __restrict__ b_out,
                      const int* __restrict__ text,
                      float* __restrict__ out) {
    extern __shared__ char smem[];
    float* GSp = (float*)(smem + SM_GS);
    const uint32_t sbase = s2u(smem);

    const int tid = threadIdx.x;
    const int lane = tid & 31, warp = tid >> 5;
    const int gid = lane >> 2, tig = lane & 3;
    const int bid = blockIdx.x;
    const int group = bid >> 5;
    const int blk = bid & 31;
    const int j0 = blk * 32;

    // loader assignments (KC=128)
    const int xrow = tid >> 2, xi = tid & 3;        // X: 64 rows, 4 uint4/thr
    const int wr = tid >> 1, wi = tid & 1;          // W: 128 rows, 8 uint4/thr
    const int wrL = tid >> 3, wiL = tid & 7;        // logits W: 32 rows, 2 uint4/thr
    // warp tiles
    const int mw = (warp & 1) * 32;
    const int nw = (warp >> 1) * 32;
    const int nwD = (warp >> 1) * 8;

    const char* wslice = (group < 3)
        ? (const char*)(g_Wpk + ((size_t)(group * 32 + blk)) * 131072)
        : (const char*)(g_Wout16 + (size_t)j0 * Hq);
    const char* wih0slice = (const char*)(g_Wpk + ((size_t)(3 * 32 + blk)) * 131072);
    const float* b_ih = (group == 0) ? bih0 : bih1;
    const float* b_hh = (group == 0) ? bhh0 : bhh1;
    float bsi = 0.f, bsf = 0.f, bsg = 0.f, bso = 0.f;
    if (group < 2) {
        int j = j0 + lane;
        bsi = b_ih[j] + b_hh[j];
        bsf = b_ih[Hq + j] + b_hh[Hq + j];
        bsg = b_ih[2 * Hq + j] + b_hh[2 * Hq + j];
        bso = b_ih[3 * Hq + j] + b_hh[3 * Hq + j];
    }

    float creg[8];
#pragma unroll
    for (int q = 0; q < 8; q++) creg[q] = 0.f;

    const int slot = (warp + bid) & 3;

    for (int s = 0; s <= 126; s++) {
        // ---- dataflow waits (pure RAW / pih-parity WAR) ----
        if (tid == 0) {
            if (group == 0) {
                if (s >= 1) waitf(g_fh0[s - 1]);
            } else if (group == 2) {
                waitf(g_fh0[s]);
                if (s >= 2) waitf(g_fh1[s - 2]);   // WAR on pih parity buffer
            } else if (group == 1) {
                waitf(g_fpih[s]);
                if (s >= 1) waitf(g_fh1[s - 1]);
            } else {
                waitf(g_fh1[s]);
            }
        }
        __syncthreads();

        const char* Xsrc;
        const char* wsl = wslice;
        bool doGemm = true;
        if (group == 0) {
            if (s == 0) { Xsrc = (const char*)g_enc16; wsl = wih0slice; }
            else Xsrc = (const char*)(g_h0h + (size_t)(s - 1) * Bq * Hq);
        } else if (group == 1) {
            doGemm = (s >= 1);
            Xsrc = doGemm ? (const char*)(g_outs16 + (size_t)(s - 1) * Bq * Hq) : nullptr;
        } else if (group == 2) {
            Xsrc = (const char*)(g_h0h + (size_t)s * Bq * Hq);
        } else {
            Xsrc = (const char*)(g_outs16 + (size_t)s * Bq * Hq);
        }

        if (group == 3) {
            // ---- logits: D[64 x 32], KC=128, 8 chunks ----
            float acc[2][4] = {};
            uint4 xv[4], wv[2];
            auto LDGD = [&](int c) {
                int cb = c * 256;
                const char* xa = Xsrc + (size_t)xrow * 2048 + cb + xi * 64;
#pragma unroll
                for (int k = 0; k < 4; k++) xv[k] = __ldcg((const uint4*)(xa + k * 16));
                const char* wa = wsl + (size_t)wrL * 2048 + cb + wiL * 32;
#pragma unroll
                for (int k = 0; k < 2; k++) wv[k] = *(const uint4*)(wa + k * 16);
            };
            auto STSD = [&](int b) {
                char* xd = smem + b * 17408 + xrow * 272 + xi * 64;
#pragma unroll
                for (int k = 0; k < 4; k++) *(uint4*)(xd + k * 16) = xv[k];
                char* wd = smem + SM_W + b * 34816 + wrL * 272 + wiL * 32;
#pragma unroll
                for (int k = 0; k < 2; k++) *(uint4*)(wd + k * 16) = wv[k];
            };
            LDGD(0);
            STSD(0);
            __syncthreads();
            for (int c = 0; c < 8; c++) {
                const int buf = c & 1;
                if (c + 1 < 8) LDGD(c + 1);
                const uint32_t xb = sbase + buf * 17408;
                const uint32_t wb = sbase + SM_W + buf * 34816;
                uint32_t hacc[2][2] = {};
#pragma unroll
                for (int ks = 0; ks < 8; ks++) {
                    int kh = ks * 16;
                    uint32_t a[2][4], b0, b1;
#pragma unroll
                    for (int ms = 0; ms < 2; ms++) {
                        uint32_t ra = xb + (mw + ms * 16 + (lane & 15)) * 272
                                    + (kh + ((lane >> 4) << 3)) * 2;
                        ldsm_x4(a[ms][0], a[ms][1], a[ms][2], a[ms][3], ra);
                    }
                    uint32_t rb = wb + (nwD + (lane & 7)) * 272
                                + (kh + (((lane >> 3) & 1) << 3)) * 2;
                    ldsm_x2(b0, b1, rb);
#pragma unroll
                    for (int ms = 0; ms < 2; ms++)
                        mma16816h(hacc[ms][0], hacc[ms][1],
                                  a[ms][0], a[ms][1], a[ms][2], a[ms][3], b0, b1);
                }
#pragma unroll
                for (int ms = 0; ms < 2; ms++)
                    promo4(acc[ms], hacc[ms][0], hacc[ms][1]);
                if (c + 1 < 8) STSD(buf ^ 1);
                __syncthreads();
            }
            int n = j0 + nwD + tig * 2;
            float bz0 = b_out[n], bz1 = b_out[n + 1];
#pragma unroll
            for (int ms = 0; ms < 2; ms++) {
                int m = mw + ms * 16 + gid;
                __stcs((float2*)&out[((size_t)m * Lq + s) * Hq + n],
                       make_float2(acc[ms][0] + bz0, acc[ms][1] + bz1));
                __stcs((float2*)&out[((size_t)(m + 8) * Lq + s) * Hq + n],
                       make_float2(acc[ms][2] + bz0, acc[ms][3] + bz1));
            }
            continue;   // no flag produced
        }

        float acc[2][4][4] = {};
        if (doGemm) {
            uint4 xv[4], wv[8];
            auto LDGC = [&](int c) {
                int cb = c * 256;
                const char* xa = Xsrc + (size_t)xrow * 2048 + cb + xi * 64;
#pragma unroll
                for (int k = 0; k < 4; k++) xv[k] = __ldcg((const uint4*)(xa + k * 16));
                const char* wa = wsl + (size_t)wr * 2048 + cb + wi * 128;
#pragma unroll
                for (int k = 0; k < 8; k++) wv[k] = *(const uint4*)(wa + k * 16);
            };
            auto STSC = [&](int b) {
                char* xd = smem + b * 17408 + xrow * 272 + xi * 64;
#pragma unroll
                for (int k = 0; k < 4; k++) *(uint4*)(xd + k * 16) = xv[k];
                char* wd = smem + SM_W + b * 34816 + wr * 272 + wi * 128;
#pragma unroll
                for (int k = 0; k < 8; k++) *(uint4*)(wd + k * 16) = wv[k];
            };

            LDGC(0);
            STSC(0);
            __syncthreads();
            for (int c = 0; c < 8; c++) {
                const int buf = c & 1;
                if (c + 1 < 8) LDGC(c + 1);
                const uint32_t xb = sbase + buf * 17408;
                const uint32_t wb = sbase + SM_W + buf * 34816;
                uint32_t hacc[2][4][2] = {};
#pragma unroll
                for (int ks = 0; ks < 8; ks++) {
                    int kh = ks * 16;
                    uint32_t a[2][4], b[2][4];
#pragma unroll
                    for (int ms = 0; ms < 2; ms++) {
                        uint32_t ra = xb + (mw + ms * 16 + (lane & 15)) * 272
                                    + (kh + ((lane >> 4) << 3)) * 2;
                        ldsm_x4(a[ms][0], a[ms][1], a[ms][2], a[ms][3], ra);
                    }
#pragma unroll
                    for (int nt2 = 0; nt2 < 2; nt2++) {
                        uint32_t rb = wb + (nw + nt2 * 16 + (lane & 7) + ((lane >> 4) << 3)) * 272
                                    + (kh + (((lane >> 3) & 1) << 3)) * 2;
                        ldsm_x4(b[nt2][0], b[nt2][1], b[nt2][2], b[nt2][3], rb);
                    }
#pragma unroll
                    for (int nt = 0; nt < 4; nt++) {
                        uint32_t b0 = b[nt >> 1][(nt & 1) * 2];
                        uint32_t b1 = b[nt >> 1][(nt & 1) * 2 + 1];
#pragma unroll
                        for (int ms = 0; ms < 2; ms++)
                            mma16816h(hacc[ms][nt][0], hacc[ms][nt][1],
                                      a[ms][0], a[ms][1], a[ms][2], a[ms][3], b0, b1);
                    }
                }
#pragma unroll
                for (int ms = 0; ms < 2; ms++)
#pragma unroll
                    for (int nt = 0; nt < 4; nt++)
                        promo4(acc[ms][nt], hacc[ms][nt][0], hacc[ms][nt][1]);
                if (c + 1 < 8) STSC(buf ^ 1);
                __syncthreads();
            }
        }

        // stage gates into GS[m][n], n = gate*32 + unit
#pragma unroll
        for (int ms = 0; ms < 2; ms++)
#pragma unroll
            for (int nt = 0; nt < 4; nt++)
#pragma unroll
                for (int hh = 0; hh < 2; hh++) {
                    int m = mw + ms * 16 + gid + hh * 8;
                    int n = nw + nt * 8 + tig * 2;
                    *(float2*)&GSp[m * 130 + n] =
                        make_float2(acc[ms][nt][hh * 2], acc[ms][nt][hh * 2 + 1]);
                }
        __syncthreads();

        if (group == 2) {
            float* pout = g_pih[s & 1];
            for (int idx = tid; idx < 8192; idx += 256) {
                int m = idx >> 7, gl = idx & 127;
                int gn = (gl >> 5) * Hq + j0 + (gl & 31);
                __stcg(&pout[(size_t)m * NG + gn], GSp[m * 130 + gl]);
            }
        } else {
            const int j = j0 + lane;
            __half* hout = (group == 0) ? (g_h0h + (size_t)s * Bq * Hq)
                                        : (g_outs16 + (size_t)s * Bq * Hq);
            const float* pin = (group == 1) ? g_pih[s & 1] : nullptr;
#pragma unroll
            for (int q = 0; q < 8; q++) {
                int m = warp + 8 * q;
                float vi = GSp[m * 130 + lane] + bsi;
                float vf = GSp[m * 130 + 32 + lane] + bsf;
                float vg = GSp[m * 130 + 64 + lane] + bsg;
                float vo = GSp[m * 130 + 96 + lane] + bso;
                if (group == 0) {
                    if (s > 0) {
                        int ix = text[m * SEQLEN + s];
                        const float* wt = g_WT + (size_t)ix * NG;
                        vi += wt[j]; vf += wt[Hq + j];
                        vg += wt[2 * Hq + j]; vo += wt[3 * Hq + j];
                    }
                } else {
                    const float* pm = pin + (size_t)m * NG;
                    vi += __ldcg(&pm[j]); vf += __ldcg(&pm[Hq + j]);
                    vg += __ldcg(&pm[2 * Hq + j]); vo += __ldcg(&pm[3 * Hq + j]);
                }
                float ig = sigf(vi), fg = sigf(vf), gg = tanhf(vg), og = sigf(vo);
                float cn = fg * creg[q] + ig * gg;
                creg[q] = cn;
                hout[m * Hq + j] = __float2half(og * tanhf(cn));
            }
        }

        // ---- per-warp release publish (no trailing block sync) ----
        __threadfence();
        if (lane == 0) {
            if (group == 0) atomicAdd(&g_fh0[s][slot], 1);
            else if (group == 2) atomicAdd(&g_fpih[s][slot], 1);
            else atomicAdd(&g_fh1[s][slot], 1);
        }
    }
}

// -------- host launch --------
extern "C" void kernel_launch(void* const* d_in, const int* in_sizes, int n_in,
                              void* d_out, int out_size) {
    const float* audio  = (const float*)d_in[0];
    const int*   text   = (const int*)d_in[1];
    const float* W_proj = (const float*)d_in[2];
    const float* b_proj = (const float*)d_in[3];
    const float* W_ih0  = (const float*)d_in[4];
    const float* W_hh0  = (const float*)d_in[5];
    const float* b_ih0  = (const float*)d_in[6];
    const float* b_hh0  = (const float*)d_in[7];
    const float* W_ih1  = (const float*)d_in[8];
    const float* W_hh1  = (const float*)d_in[9];
    const float* b_ih1  = (const float*)d_in[10];
    const float* b_hh1  = (const float*)d_in[11];
    const float* W_out  = (const float*)d_in[12];
    const float* b_out  = (const float*)d_in[13];
    float* out = (float*)d_out;

    cudaFuncSetAttribute(lstm_fp16_kernel,
                         cudaFuncAttributeMaxDynamicSharedMemorySize, SMEM_BYTES);

    reset_kernel<<<2, 256>>>();
    pool_kernel<<<(Bq * DIN) / 128, 128>>>(audio);
    transpose_kernel<<<dim3(32, 128), dim3(32, 8)>>>(W_ih0);
    pack_w16_kernel<<<512, 256>>>(W_hh0, W_hh1, W_ih1, W_ih0);
    pack_wout_kernel<<<1024, 256>>>(W_out);
    gemm_enc_kernel<<<16, 256>>>(W_proj, b_proj, DIN);

    lstm_fp16_kernel<<<NPB, 256, SMEM_BYTES>>>(b_ih0, b_hh0, b_ih1, b_hh1,
                                               b_out, text, out);
}

// round 15
// speedup vs baseline: 1.6257x; 1.6257x over previous
#include <cuda_runtime.h>
#include <cuda_fp16.h>
#include <cstdint>

#define Bq 64
#define Hq 1024
#define NG 4096
#define DIN 768
#define TAUD 500
#define Lq 127
#define SEQLEN 128
#define NPB 128       // 4 groups x 32 blocks

// ---- dynamic smem layout (bytes) ----
// X bufs: 2 x (64 rows x 72 halves)  = 2 x 9216
// W bufs: 2 x (128 rows x 72 halves) = 2 x 18432
// GS:     64 x 130 floats            = 33280
#define SM_WOFF 18432
#define SM_GSOFF 55296
#define SMEM_BYTES 88576

// -------- scratch --------
__device__ float g_pooled[Bq * DIN];
__device__ __half g_enc16[Bq * Hq];
__device__ float g_WT[Hq * NG];                    // Wih0^T: [char][gate-row]
__device__ __half g_Wpk[4u * 32u * 128u * 1024u];  // Whh0, Whh1, Wih1, Wih0
__device__ __half g_Wout16[Hq * Hq];               // fp16 W_out [n][k]
__device__ __half g_h0h[(size_t)Lq * Bq * Hq];     // h0 full history
__device__ __half g_outs16[(size_t)Lq * Bq * Hq];  // h1 history == outputs
__device__ float g_pih[2][Bq * NG];                // layer1 partial ih gates
__device__ int g_fh0[Lq];
__device__ int g_fpih[Lq];
__device__ int g_fh1[Lq];

__device__ __forceinline__ float sigf(float x) { return 1.0f / (1.0f + __expf(-x)); }

__device__ __forceinline__ uint32_t h2_as_u32(__half2 h) {
    return *reinterpret_cast<uint32_t*>(&h);
}

__device__ __forceinline__ uint32_t s2u(const void* p) {
    uint32_t a;
    asm("{ .reg .u64 t; cvta.to.shared.u64 t, %1; cvt.u32.u64 %0, t; }" : "=r"(a) : "l"(p));
    return a;
}

__device__ __forceinline__ uint32_t f2tf32(float f) {
    uint32_t u;
    asm("cvt.rna.tf32.f32 %0, %1;" : "=r"(u) : "f"(f));
    return u;
}

__device__ __forceinline__ void ldsm_x4(uint32_t& r0, uint32_t& r1, uint32_t& r2, uint32_t& r3,
                                        uint32_t addr) {
    asm volatile("ldmatrix.sync.aligned.m8n8.x4.shared.b16 {%0,%1,%2,%3}, [%4];"
                 : "=r"(r0), "=r"(r1), "=r"(r2), "=r"(r3) : "r"(addr));
}
__device__ __forceinline__ void ldsm_x2(uint32_t& r0, uint32_t& r1, uint32_t addr) {
    asm volatile("ldmatrix.sync.aligned.m8n8.x2.shared.b16 {%0,%1}, [%2];"
                 : "=r"(r0), "=r"(r1) : "r"(addr));
}

// fp16 mma with fp16 accumulators (packed half2 x2)
__device__ __forceinline__ void mma16816h(uint32_t& d0, uint32_t& d1,
                                          uint32_t a0, uint32_t a1, uint32_t a2, uint32_t a3,
                                          uint32_t b0, uint32_t b1) {
    asm volatile("mma.sync.aligned.m16n8k16.row.col.f16.f16.f16.f16 "
                 "{%0,%1}, {%2,%3,%4,%5}, {%6,%7}, {%0,%1};"
                 : "+r"(d0), "+r"(d1)
                 : "r"(a0), "r"(a1), "r"(a2), "r"(a3), "r"(b0), "r"(b1));
}

// promote packed f16 pair into 4 f32 accumulators
__device__ __forceinline__ void promo4(float* a4, uint32_t h0, uint32_t h1) {
    float2 lo = __half22float2(*reinterpret_cast<__half2*>(&h0));
    float2 hi = __half22float2(*reinterpret_cast<__half2*>(&h1));
    a4[0] += lo.x; a4[1] += lo.y; a4[2] += hi.x; a4[3] += hi.y;
}

// tf32 SIMT mma (prologue GEMM)
__device__ __forceinline__ void mma_tf32(float& c0, float& c1, float& c2, float& c3,
                                         uint32_t a0, uint32_t a1, uint32_t a2, uint32_t a3,
                                         uint32_t b0, uint32_t b1) {
    asm volatile("mma.sync.aligned.m16n8k8.row.col.f32.tf32.tf32.f32 "
                 "{%0,%1,%2,%3}, {%4,%5,%6,%7}, {%8,%9}, {%0,%1,%2,%3};"
                 : "+f"(c0), "+f"(c1), "+f"(c2), "+f"(c3)
                 : "r"(a0), "r"(a1), "r"(a2), "r"(a3), "r"(b0), "r"(b1));
}

__device__ __forceinline__ void waitflag(const int* f, int need) {
    int v;
    do {
        asm volatile("ld.acquire.gpu.s32 %0, [%1];" : "=r"(v) : "l"(f));
    } while (v < need);
}

__global__ void reset_kernel() {
    int i = threadIdx.x;
    if (i < Lq) { g_fh0[i] = 0; g_fpih[i] = 0; g_fh1[i] = 0; }
}

// -------- mean-pool audio --------
__global__ void pool_kernel(const float* __restrict__ audio) {
    int i = blockIdx.x * blockDim.x + threadIdx.x;
    int b = i / DIN, d = i % DIN;
    const float* p = audio + (size_t)b * TAUD * DIN + d;
    float s = 0.f;
#pragma unroll 5
    for (int t = 0; t < TAUD; t++) s += __ldcs(p + (size_t)t * DIN);
    g_pooled[i] = s * (1.0f / TAUD);
}

// -------- transpose Wih0 -> WT[char][gate-row] --------
__global__ void transpose_kernel(const float* __restrict__ W) {
    __shared__ float tile[32][33];
    int bx = blockIdx.x, by = blockIdx.y;
    int tx = threadIdx.x, ty0 = threadIdx.y;
#pragma unroll
    for (int q = 0; q < 4; q++) {
        int ty = ty0 + q * 8;
        tile[ty][tx] = W[(size_t)(by * 32 + ty) * Hq + bx * 32 + tx];
    }
    __syncthreads();
#pragma unroll
    for (int q = 0; q < 4; q++) {
        int ty = ty0 + q * 8;
        g_WT[(size_t)(bx * 32 + ty) * NG + by * 32 + tx] = tile[tx][ty];
    }
}

// -------- pack weights to fp16 per-(grp,blk) slices: row = gate*32+unit --------
__global__ void pack_w16_kernel(const float* __restrict__ W0,
                                const float* __restrict__ W1,
                                const float* __restrict__ W2,
                                const float* __restrict__ W3) {
    int id = blockIdx.x;              // 0..511
    int grp = id >> 7;
    int rem = id & 127;
    int blk = rem >> 2;
    int qtr = rem & 3;
    const float* W = (grp == 0) ? W0 : (grp == 1 ? W1 : (grp == 2 ? W2 : W3));
    int j0 = blk * 32;
    __half* dst = g_Wpk + ((size_t)(grp * 32 + blk)) * 131072;
    int f4e = (qtr + 1) * 8192;
    for (int f4 = qtr * 8192 + threadIdx.x; f4 < f4e; f4 += 256) {
        int r = f4 >> 8;
        int c = (f4 & 255) * 4;
        int grow = (r >> 5) * Hq + j0 + (r & 31);
        float4 v = *(const float4*)(W + (size_t)grow * Hq + c);
        uint2 o;
        o.x = h2_as_u32(__floats2half2_rn(v.x, v.y));
        o.y = h2_as_u32(__floats2half2_rn(v.z, v.w));
        *(uint2*)(dst + (size_t)r * 1024 + c) = o;
    }
}

// -------- pack W_out to fp16 row-major --------
__global__ void pack_wout_kernel(const float* __restrict__ W) {
    int i = blockIdx.x * blockDim.x + threadIdx.x;
    float4 v = *(const float4*)(W + (size_t)i * 4);
    uint2 o;
    o.x = h2_as_u32(__floats2half2_rn(v.x, v.y));
    o.y = h2_as_u32(__floats2half2_rn(v.z, v.w));
    *(uint2*)(g_Wout16 + (size_t)i * 4) = o;
}

// ============ SIMT tf32 GEMM: enc = pooled @ W_proj^T + b -> fp16 [m][k] ============
__global__ __launch_bounds__(256, 2)
void gemm_enc_kernel(const float* __restrict__ Bw,
                     const float* __restrict__ bias, int K) {
    __shared__ uint32_t As[64][36];
    __shared__ uint32_t Bs[64][36];
    const float* A = g_pooled;

    int tid = threadIdx.x;
    int lane = tid & 31, warp = tid >> 5;
    int nblk = blockIdx.x;
    int m0 = (warp & 3) * 16;
    int n0 = (warp >> 2) * 32;
    float acc[4][4] = {};
    int row = tid >> 3;
    int c4 = (tid & 7) * 4;

    const float* ap0 = A + (size_t)row * K + c4;
    const float* ap1 = A + (size_t)(row + 32) * K + c4;
    const float* bp0 = Bw + (size_t)(nblk * 64 + row) * K + c4;
    const float* bp1 = Bw + (size_t)(nblk * 64 + row + 32) * K + c4;

    int nC = K / 32;
    float4 xv0 = *(const float4*)ap0;
    float4 xv1 = *(const float4*)ap1;
    float4 wv0 = *(const float4*)bp0;
    float4 wv1 = *(const float4*)bp1;

    for (int c = 0; c < nC; c++) {
        uint4 u;
        u.x = f2tf32(xv0.x); u.y = f2tf32(xv0.y); u.z = f2tf32(xv0.z); u.w = f2tf32(xv0.w);
        *(uint4*)&As[row][c4] = u;
        u.x = f2tf32(xv1.x); u.y = f2tf32(xv1.y); u.z = f2tf32(xv1.z); u.w = f2tf32(xv1.w);
        *(uint4*)&As[row + 32][c4] = u;
        u.x = f2tf32(wv0.x); u.y = f2tf32(wv0.y); u.z = f2tf32(wv0.z); u.w = f2tf32(wv0.w);
        *(uint4*)&Bs[row][c4] = u;
        u.x = f2tf32(wv1.x); u.y = f2tf32(wv1.y); u.z = f2tf32(wv1.z); u.w = f2tf32(wv1.w);
        *(uint4*)&Bs[row + 32][c4] = u;
        __syncthreads();

        if (c + 1 < nC) {
            int k0 = (c + 1) * 32;
            xv0 = *(const float4*)(ap0 + k0);
            xv1 = *(const float4*)(ap1 + k0);
            wv0 = *(const float4*)(bp0 + k0);
            wv1 = *(const float4*)(bp1 + k0);
        }
#pragma unroll
        for (int ks = 0; ks < 4; ks++) {
            int kk = ks * 8;
            uint32_t a0 = As[m0 + (lane >> 2)][kk + (lane & 3)];
            uint32_t a1 = As[m0 + (lane >> 2) + 8][kk + (lane & 3)];
            uint32_t a2 = As[m0 + (lane >> 2)][kk + (lane & 3) + 4];
            uint32_t a3 = As[m0 + (lane >> 2) + 8][kk + (lane & 3) + 4];
#pragma unroll
            for (int nt = 0; nt < 4; nt++) {
                uint32_t b0 = Bs[n0 + nt * 8 + (lane >> 2)][kk + (lane & 3)];
                uint32_t b1 = Bs[n0 + nt * 8 + (lane >> 2)][kk + (lane & 3) + 4];
                mma_tf32(acc[nt][0], acc[nt][1], acc[nt][2], acc[nt][3],
                         a0, a1, a2, a3, b0, b1);
            }
        }
        __syncthreads();
    }

#pragma unroll
    for (int nt = 0; nt < 4; nt++) {
        int r = m0 + (lane >> 2);
        int cc = nblk * 64 + n0 + nt * 8 + (lane & 3) * 2;
        float bz0 = bias[cc], bz1 = bias[cc + 1];
        *(uint32_t*)&g_enc16[r * Hq + cc] =
            h2_as_u32(__floats2half2_rn(acc[nt][0] + bz0, acc[nt][1] + bz1));
        *(uint32_t*)&g_enc16[(r + 8) * Hq + cc] =
            h2_as_u32(__floats2half2_rn(acc[nt][2] + bz0, acc[nt][3] + bz1));
    }
}

// ============ persistent 4-group dataflow LSTM + logits ============
// grp0 [0,32):  h0(s)           grp1 [32,64): h1(s) = hh-GEMM + pih + epi
// grp2 [64,96): pih(s)          grp3 [96,128): logits(s), N=32 cols
__global__ __launch_bounds__(256, 1)
void lstm_fp16_kernel(const float* __restrict__ bih0, const float* __restrict__ bhh0,
                      const float* __restrict__ bih1, const float* __restrict__ bhh1,
                      const float* __restrict__ b_out,
                      const int* __restrict__ text,
                      float* __restrict__ out) {
    extern __shared__ char smem[];
    float* GSp = (float*)(smem + SM_GSOFF);
    const uint32_t sbase = s2u(smem);

    const int tid = threadIdx.x;
    const int lane = tid & 31, warp = tid >> 5;
    const int gid = lane >> 2, tig = lane & 3;
    const int bid = blockIdx.x;
    const int group = bid >> 5;
    const int blk = bid & 31;
    const int j0 = blk * 32;

    const char* wslice = (group < 3)
        ? (const char*)(g_Wpk + ((size_t)(group * 32 + blk)) * 131072)
        : (const char*)(g_Wout16 + (size_t)j0 * Hq);
    const char* wih0slice = (const char*)(g_Wpk + ((size_t)(3 * 32 + blk)) * 131072);
    const float* b_ih = (group == 0) ? bih0 : bih1;
    const float* b_hh = (group == 0) ? bhh0 : bhh1;
    float bsi = 0.f, bsf = 0.f, bsg = 0.f, bso = 0.f;
    if (group < 2) {
        int j = j0 + lane;
        bsi = b_ih[j] + b_hh[j];
        bsf = b_ih[Hq + j] + b_hh[Hq + j];
        bsg = b_ih[2 * Hq + j] + b_hh[2 * Hq + j];
        bso = b_ih[3 * Hq + j] + b_hh[3 * Hq + j];
    }

    // loader assignments
    const int xrow = tid >> 3;         // 0..31 (+32 for second X row batch)
    const int xu = tid & 7;            // uint4 slot within 64-half row-chunk
    // warp tiles
    const int mw = (warp & 1) * 32;          // batch half
    const int nw = (warp >> 1) * 32;         // main: 32 gate-rows
    const int nwD = (warp >> 1) * 8;         // grp3: 8 logit cols

    float creg[8];
#pragma unroll
    for (int q = 0; q < 8; q++) creg[q] = 0.f;

    for (int s = 0; s <= 126; s++) {
        // ---- dataflow waits ----
        if (tid == 0) {
            if (group == 0) {
                if (s >= 1) waitflag(&g_fh0[s - 1], 32);
            } else if (group == 2) {
                waitflag(&g_fh0[s], 32);
                if (s >= 2) waitflag(&g_fh1[s - 2], 32);   // WAR on pih parity
            } else if (group == 1) {
                waitflag(&g_fpih[s], 32);
                if (s >= 1) waitflag(&g_fh1[s - 1], 32);
            } else {
                waitflag(&g_fh1[s], 32);
            }
        }
        __syncthreads();

        const char* Xsrc;
        const char* wsl = wslice;
        bool doGemm = true;
        if (group == 0) {
            if (s == 0) { Xsrc = (const char*)g_enc16; wsl = wih0slice; }
            else Xsrc = (const char*)(g_h0h + (size_t)(s - 1) * Bq * Hq);
        } else if (group == 1) {
            doGemm = (s >= 1);
            Xsrc = doGemm ? (const char*)(g_outs16 + (size_t)(s - 1) * Bq * Hq) : nullptr;
        } else if (group == 2) {
            Xsrc = (const char*)(g_h0h + (size_t)s * Bq * Hq);
        } else {
            Xsrc = (const char*)(g_outs16 + (size_t)s * Bq * Hq);
        }

        if (group == 3) {
            // ---- logits: D[64 x 32] = outs16[s] @ Wout[j0:j0+32]^T ----
            float acc[2][4] = {};
            uint4 xv[2], wv;
            auto LDGD = [&](int c) {
                int cb = c * 128;
#pragma unroll
                for (int i = 0; i < 2; i++)
                    xv[i] = __ldcg((const uint4*)(Xsrc + (size_t)(xrow + 32 * i) * 2048 + cb + xu * 16));
                wv = *(const uint4*)(wsl + (size_t)xrow * 2048 + cb + xu * 16);
            };
            auto STSD = [&](int b) {
#pragma unroll
                for (int i = 0; i < 2; i++)
                    *(uint4*)(smem + b * 9216 + (xrow + 32 * i) * 144 + xu * 16) = xv[i];
                *(uint4*)(smem + SM_WOFF + b * 18432 + xrow * 144 + xu * 16) = wv;
            };
            LDGD(0);
            STSD(0);
            __syncthreads();
            for (int c = 0; c < 16; c++) {
                const int buf = c & 1;
                if (c + 1 < 16) LDGD(c + 1);
                const uint32_t xb = sbase + buf * 9216;
                const uint32_t wb = sbase + SM_WOFF + buf * 18432;
                uint32_t hacc[2][2] = {};
#pragma unroll
                for (int ks = 0; ks < 4; ks++) {
                    int kh = ks * 16;
                    uint32_t a[2][4], b0, b1;
#pragma unroll
                    for (int ms = 0; ms < 2; ms++) {
                        uint32_t ra = xb + (mw + ms * 16 + (lane & 15)) * 144
                                    + (kh + ((lane >> 4) << 3)) * 2;
                        ldsm_x4(a[ms][0], a[ms][1], a[ms][2], a[ms][3], ra);
                    }
                    uint32_t rb = wb + (nwD + (lane & 7)) * 144
                                + (kh + (((lane >> 3) & 1) << 3)) * 2;
                    ldsm_x2(b0, b1, rb);
#pragma unroll
                    for (int ms = 0; ms < 2; ms++)
                        mma16816h(hacc[ms][0], hacc[ms][1],
                                  a[ms][0], a[ms][1], a[ms][2], a[ms][3], b0, b1);
                }
#pragma unroll
                for (int ms = 0; ms < 2; ms++)
                    promo4(acc[ms], hacc[ms][0], hacc[ms][1]);
                if (c + 1 < 16) STSD(buf ^ 1);
                __syncthreads();
            }
            int n = j0 + nwD + tig * 2;
            float bz0 = b_out[n], bz1 = b_out[n + 1];
#pragma unroll
            for (int ms = 0; ms < 2; ms++) {
                int m = mw + ms * 16 + gid;
                __stcs((float2*)&out[((size_t)m * Lq + s) * Hq + n],
                       make_float2(acc[ms][0] + bz0, acc[ms][1] + bz1));
                __stcs((float2*)&out[((size_t)(m + 8) * Lq + s) * Hq + n],
                       make_float2(acc[ms][2] + bz0, acc[ms][3] + bz1));
            }
            __syncthreads();
            continue;
        }

        float acc[2][4][4] = {};
        if (doGemm) {
            uint4 xv[2], wv[4];
            auto LDGC = [&](int c) {
                int cb = c * 128;
#pragma unroll
                for (int i = 0; i < 2; i++)
                    xv[i] = __ldcg((const uint4*)(Xsrc + (size_t)(xrow + 32 * i) * 2048 + cb + xu * 16));
#pragma unroll
                for (int i = 0; i < 4; i++)
                    wv[i] = *(const uint4*)(wsl + (size_t)(xrow + 32 * i) * 2048 + cb + xu * 16);
            };
            auto STSC = [&](int b) {
#pragma unroll
                for (int i = 0; i < 2; i++)
                    *(uint4*)(smem + b * 9216 + (xrow + 32 * i) * 144 + xu * 16) = xv[i];
#pragma unroll
                for (int i = 0; i < 4; i++)
                    *(uint4*)(smem + SM_WOFF + b * 18432 + (xrow + 32 * i) * 144 + xu * 16) = wv[i];
            };

            LDGC(0);
            STSC(0);
            __syncthreads();
            for (int c = 0; c < 16; c++) {
                const int buf = c & 1;
                if (c + 1 < 16) LDGC(c + 1);
                const uint32_t xb = sbase + buf * 9216;
                const uint32_t wb = sbase + SM_WOFF + buf * 18432;
                uint32_t hacc[2][4][2] = {};
#pragma unroll
                for (int ks = 0; ks < 4; ks++) {
                    int kh = ks * 16;
                    uint32_t a[2][4], b[2][4];
#pragma unroll
                    for (int ms = 0; ms < 2; ms++) {
                        uint32_t ra = xb + (mw + ms * 16 + (lane & 15)) * 144
                                    + (kh + ((lane >> 4) << 3)) * 2;
                        ldsm_x4(a[ms][0], a[ms][1], a[ms][2], a[ms][3], ra);
                    }
#pragma unroll
                    for (int nt2 = 0; nt2 < 2; nt2++) {
                        uint32_t rb = wb + (nw + nt2 * 16 + (lane & 7) + ((lane >> 4) << 3)) * 144
                                    + (kh + (((lane >> 3) & 1) << 3)) * 2;
                        ldsm_x4(b[nt2][0], b[nt2][1], b[nt2][2], b[nt2][3], rb);
                    }
#pragma unroll
                    for (int nt = 0; nt < 4; nt++) {
                        uint32_t b0 = b[nt >> 1][(nt & 1) * 2];
                        uint32_t b1 = b[nt >> 1][(nt & 1) * 2 + 1];
#pragma unroll
                        for (int ms = 0; ms < 2; ms++)
                            mma16816h(hacc[ms][nt][0], hacc[ms][nt][1],
                                      a[ms][0], a[ms][1], a[ms][2], a[ms][3], b0, b1);
                    }
                }
#pragma unroll
                for (int ms = 0; ms < 2; ms++)
#pragma unroll
                    for (int nt = 0; nt < 4; nt++)
                        promo4(acc[ms][nt], hacc[ms][nt][0], hacc[ms][nt][1]);
                if (c + 1 < 16) STSC(buf ^ 1);
                __syncthreads();
            }
        }

        // stage gates into GS[m][r]  (m batch, r = gate*32 + unit)
#pragma unroll
        for (int ms = 0; ms < 2; ms++)
#pragma unroll
            for (int nt = 0; nt < 4; nt++)
#pragma unroll
                for (int hh = 0; hh < 2; hh++) {
                    int m = mw + ms * 16 + gid + hh * 8;
                    int r = nw + nt * 8 + tig * 2;
                    *(float2*)&GSp[m * 130 + r] =
                        make_float2(acc[ms][nt][hh * 2], acc[ms][nt][hh * 2 + 1]);
                }
        __syncthreads();

        if (group == 2) {
            float* pout = g_pih[s & 1];
            for (int idx = tid; idx < 8192; idx += 256) {
                int m = idx >> 7, gl = idx & 127;
                int gn = (gl >> 5) * Hq + j0 + (gl & 31);
                __stcg(&pout[(size_t)m * NG + gn], GSp[m * 130 + gl]);
            }
        } else {
            const int j = j0 + lane;
            __half* hout = (group == 0) ? (g_h0h + (size_t)s * Bq * Hq)
                                        : (g_outs16 + (size_t)s * Bq * Hq);
            const float* pin = (group == 1) ? g_pih[s & 1] : nullptr;
#pragma unroll
            for (int q = 0; q < 8; q++) {
                int m = warp + 8 * q;
                float vi = GSp[m * 130 + lane] + bsi;
                float vf = GSp[m * 130 + 32 + lane] + bsf;
                float vg = GSp[m * 130 + 64 + lane] + bsg;
                float vo = GSp[m * 130 + 96 + lane] + bso;
                if (group == 0) {
                    if (s > 0) {
                        int ix = text[m * SEQLEN + s];
                        const float* wt = g_WT + (size_t)ix * NG;
                        vi += wt[j]; vf += wt[Hq + j];
                        vg += wt[2 * Hq + j]; vo += wt[3 * Hq + j];
                    }
                } else {
                    const float* pm = pin + (size_t)m * NG;
                    vi += __ldcg(&pm[j]); vf += __ldcg(&pm[Hq + j]);
                    vg += __ldcg(&pm[2 * Hq + j]); vo += __ldcg(&pm[3 * Hq + j]);
                }
                float ig = sigf(vi), fg = sigf(vf), gg = tanhf(vg), og = sigf(vo);
                float cn = fg * creg[q] + ig * gg;
                creg[q] = cn;
                hout[m * Hq + j] = __float2half(og * tanhf(cn));
            }
        }
        __syncthreads();

        // ---- publish completion flag ----
        if (tid == 0) {
            __threadfence();
            if (group == 0) atomicAdd(&g_fh0[s], 1);
            else if (group == 2) atomicAdd(&g_fpih[s], 1);
            else atomicAdd(&g_fh1[s], 1);
        }
    }
}

// -------- host launch --------
extern "C" void kernel_launch(void* const* d_in, const int* in_sizes, int n_in,
                              void* d_out, int out_size) {
    const float* audio  = (const float*)d_in[0];
    const int*   text   = (const int*)d_in[1];
    const float* W_proj = (const float*)d_in[2];
    const float* b_proj = (const float*)d_in[3];
    const float* W_ih0  = (const float*)d_in[4];
    const float* W_hh0  = (const float*)d_in[5];
    const float* b_ih0  = (const float*)d_in[6];
    const float* b_hh0  = (const float*)d_in[7];
    const float* W_ih1  = (const float*)d_in[8];
    const float* W_hh1  = (const float*)d_in[9];
    const float* b_ih1  = (const float*)d_in[10];
    const float* b_hh1  = (const float*)d_in[11];
    const float* W_out  = (const float*)d_in[12];
    const float* b_out  = (const float*)d_in[13];
    float* out = (float*)d_out;

    cudaFuncSetAttribute(lstm_fp16_kernel,
                         cudaFuncAttributeMaxDynamicSharedMemorySize, SMEM_BYTES);

    reset_kernel<<<1, 128>>>();
    pool_kernel<<<(Bq * DIN) / 128, 128>>>(audio);
    transpose_kernel<<<dim3(32, 128), dim3(32, 8)>>>(W_ih0);
    pack_w16_kernel<<<512, 256>>>(W_hh0, W_hh1, W_ih1, W_ih0);
    pack_wout_kernel<<<1024, 256>>>(W_out);
    gemm_enc_kernel<<<16, 256>>>(W_proj, b_proj, DIN);

    lstm_fp16_kernel<<<NPB, 256, SMEM_BYTES>>>(b_ih0, b_hh0, b_ih1, b_hh1,
                                               b_out, text, out);
}

// round 16
// speedup vs baseline: 1.6741x; 1.0298x over previous
#include <cuda_runtime.h>
#include <cuda_fp16.h>
#include <cstdint>

#define Bq 64
#define Hq 1024
#define NG 4096
#define DIN 768
#define TAUD 500
#define Lq 127
#define SEQLEN 128
#define NPB 128       // 4 groups x 32 blocks

// ---- dynamic smem layout (bytes) ----
#define SM_WOFF 18432
#define SM_GSOFF 55296
#define SMEM_BYTES 88576

// -------- scratch --------
__device__ float g_pooled[Bq * DIN];
__device__ __half g_enc16[Bq * Hq];
__device__ float g_WT[Hq * NG];                    // Wih0^T: [char][gate-row]
__device__ __half g_Wpk[4u * 32u * 128u * 1024u];  // Whh0, Whh1, Wih1, Wih0
__device__ __half g_Wout16[Hq * Hq];               // fp16 W_out [n][k]
__device__ __half g_h0h[(size_t)Lq * Bq * Hq];     // h0 full history
__device__ __half g_outs16[(size_t)Lq * Bq * Hq];  // h1 history == outputs
__device__ __half g_pih[2][Bq * NG];               // layer1 partial ih gates (fp16)
__device__ int g_fh0[Lq];
__device__ int g_fpih[Lq];
__device__ int g_fh1[Lq];

__device__ __forceinline__ float sigf(float x) { return 1.0f / (1.0f + __expf(-x)); }

__device__ __forceinline__ uint32_t h2_as_u32(__half2 h) {
    return *reinterpret_cast<uint32_t*>(&h);
}

__device__ __forceinline__ uint32_t s2u(const void* p) {
    uint32_t a;
    asm("{ .reg .u64 t; cvta.to.shared.u64 t, %1; cvt.u32.u64 %0, t; }" : "=r"(a) : "l"(p));
    return a;
}

__device__ __forceinline__ uint32_t f2tf32(float f) {
    uint32_t u;
    asm("cvt.rna.tf32.f32 %0, %1;" : "=r"(u) : "f"(f));
    return u;
}

__device__ __forceinline__ void ldsm_x4(uint32_t& r0, uint32_t& r1, uint32_t& r2, uint32_t& r3,
                                        uint32_t addr) {
    asm volatile("ldmatrix.sync.aligned.m8n8.x4.shared.b16 {%0,%1,%2,%3}, [%4];"
                 : "=r"(r0), "=r"(r1), "=r"(r2), "=r"(r3) : "r"(addr));
}
__device__ __forceinline__ void ldsm_x2(uint32_t& r0, uint32_t& r1, uint32_t addr) {
    asm volatile("ldmatrix.sync.aligned.m8n8.x2.shared.b16 {%0,%1}, [%2];"
                 : "=r"(r0), "=r"(r1) : "r"(addr));
}

// fp16 mma with fp16 accumulators (packed half2 x2)
__device__ __forceinline__ void mma16816h(uint32_t& d0, uint32_t& d1,
                                          uint32_t a0, uint32_t a1, uint32_t a2, uint32_t a3,
                                          uint32_t b0, uint32_t b1) {
    asm volatile("mma.sync.aligned.m16n8k16.row.col.f16.f16.f16.f16 "
                 "{%0,%1}, {%2,%3,%4,%5}, {%6,%7}, {%0,%1};"
                 : "+r"(d0), "+r"(d1)
                 : "r"(a0), "r"(a1), "r"(a2), "r"(a3), "r"(b0), "r"(b1));
}

// promote packed f16 pair into 4 f32 accumulators
__device__ __forceinline__ void promo4(float* a4, uint32_t h0, uint32_t h1) {
    float2 lo = __half22float2(*reinterpret_cast<__half2*>(&h0));
    float2 hi = __half22float2(*reinterpret_cast<__half2*>(&h1));
    a4[0] += lo.x; a4[1] += lo.y; a4[2] += hi.x; a4[3] += hi.y;
}

// tf32 SIMT mma (prologue GEMM)
__device__ __forceinline__ void mma_tf32(float& c0, float& c1, float& c2, float& c3,
                                         uint32_t a0, uint32_t a1, uint32_t a2, uint32_t a3,
                                         uint32_t b0, uint32_t b1) {
    asm volatile("mma.sync.aligned.m16n8k8.row.col.f32.tf32.tf32.f32 "
                 "{%0,%1,%2,%3}, {%4,%5,%6,%7}, {%8,%9}, {%0,%1,%2,%3};"
                 : "+f"(c0), "+f"(c1), "+f"(c2), "+f"(c3)
                 : "r"(a0), "r"(a1), "r"(a2), "r"(a3), "r"(b0), "r"(b1));
}

__device__ __forceinline__ void waitflag(const int* f, int need) {
    int v;
    do {
        asm volatile("ld.acquire.gpu.s32 %0, [%1];" : "=r"(v) : "l"(f));
    } while (v < need);
}

// ============ fused prologue: reset | pool | transpose | pack W | pack Wout ============
// block ranges: [0,2) reset flags | [2,194) pool | [194,706) pack_w16 |
//               [706,1730) pack_wout | [1730,5826) transpose (4096 tiles)
__global__ __launch_bounds__(256)
void prep_kernel(const float* __restrict__ audio,
                 const float* __restrict__ W0, const float* __restrict__ W1,
                 const float* __restrict__ W2, const float* __restrict__ W3,
                 const float* __restrict__ Wout) {
    const int b = blockIdx.x;
    const int tid = threadIdx.x;

    if (b < 2) {                      // ---- reset flags ----
        int i = b * 256 + tid;
        if (i < Lq) { g_fh0[i] = 0; g_fpih[i] = 0; g_fh1[i] = 0; }
        return;
    }
    if (b < 194) {                    // ---- mean-pool audio ----
        int i = (b - 2) * 256 + tid;  // B*DIN = 49152
        int bb = i / DIN, d = i % DIN;
        const float* p = audio + (size_t)bb * TAUD * DIN + d;
        float s = 0.f;
#pragma unroll 5
        for (int t = 0; t < TAUD; t++) s += __ldcs(p + (size_t)t * DIN);
        g_pooled[i] = s * (1.0f / TAUD);
        return;
    }
    if (b < 706) {                    // ---- pack LSTM weights to fp16 slices ----
        int id = b - 194;             // 0..511
        int grp = id >> 7;
        int rem = id & 127;
        int blk = rem >> 2;
        int qtr = rem & 3;
        const float* W = (grp == 0) ? W0 : (grp == 1 ? W1 : (grp == 2 ? W2 : W3));
        int j0 = blk * 32;
        __half* dst = g_Wpk + ((size_t)(grp * 32 + blk)) * 131072;
        int f4e = (qtr + 1) * 8192;
        for (int f4 = qtr * 8192 + tid; f4 < f4e; f4 += 256) {
            int r = f4 >> 8;
            int c = (f4 & 255) * 4;
            int grow = (r >> 5) * Hq + j0 + (r & 31);
            float4 v = *(const float4*)(W + (size_t)grow * Hq + c);
            uint2 o;
            o.x = h2_as_u32(__floats2half2_rn(v.x, v.y));
            o.y = h2_as_u32(__floats2half2_rn(v.z, v.w));
            *(uint2*)(dst + (size_t)r * 1024 + c) = o;
        }
        return;
    }
    if (b < 1730) {                   // ---- pack W_out to fp16 ----
        int i = (b - 706) * 256 + tid;
        float4 v = *(const float4*)(Wout + (size_t)i * 4);
        uint2 o;
        o.x = h2_as_u32(__floats2half2_rn(v.x, v.y));
        o.y = h2_as_u32(__floats2half2_rn(v.z, v.w));
        *(uint2*)(g_Wout16 + (size_t)i * 4) = o;
        return;
    }
    {                                 // ---- transpose Wih0 -> WT[char][gate-row] ----
        __shared__ float tile[32][33];
        int t32 = b - 1730;           // 0..4095
        int bx = t32 & 31, by = t32 >> 5;   // bx: char tile, by: row tile
        int tx = tid & 31, ty0 = tid >> 5;  // 32 x 8
#pragma unroll
        for (int q = 0; q < 4; q++) {
            int ty = ty0 + q * 8;
            tile[ty][tx] = W2 == nullptr ? 0.f :
                W3[(size_t)(by * 32 + ty) * Hq + bx * 32 + tx];
        }
        __syncthreads();
#pragma unroll
        for (int q = 0; q < 4; q++) {
            int ty = ty0 + q * 8;
            g_WT[(size_t)(bx * 32 + ty) * NG + by * 32 + tx] = tile[tx][ty];
        }
        return;
    }
}

// ============ SIMT tf32 GEMM: enc = pooled @ W_proj^T + b -> fp16 [m][k] ============
__global__ __launch_bounds__(256, 2)
void gemm_enc_kernel(const float* __restrict__ Bw,
                     const float* __restrict__ bias, int K) {
    __shared__ uint32_t As[64][36];
    __shared__ uint32_t Bs[64][36];
    const float* A = g_pooled;

    int tid = threadIdx.x;
    int lane = tid & 31, warp = tid >> 5;
    int nblk = blockIdx.x;
    int m0 = (warp & 3) * 16;
    int n0 = (warp >> 2) * 32;
    float acc[4][4] = {};
    int row = tid >> 3;
    int c4 = (tid & 7) * 4;

    const float* ap0 = A + (size_t)row * K + c4;
    const float* ap1 = A + (size_t)(row + 32) * K + c4;
    const float* bp0 = Bw + (size_t)(nblk * 64 + row) * K + c4;
    const float* bp1 = Bw + (size_t)(nblk * 64 + row + 32) * K + c4;

    int nC = K / 32;
    float4 xv0 = *(const float4*)ap0;
    float4 xv1 = *(const float4*)ap1;
    float4 wv0 = *(const float4*)bp0;
    float4 wv1 = *(const float4*)bp1;

    for (int c = 0; c < nC; c++) {
        uint4 u;
        u.x = f2tf32(xv0.x); u.y = f2tf32(xv0.y); u.z = f2tf32(xv0.z); u.w = f2tf32(xv0.w);
        *(uint4*)&As[row][c4] = u;
        u.x = f2tf32(xv1.x); u.y = f2tf32(xv1.y); u.z = f2tf32(xv1.z); u.w = f2tf32(xv1.w);
        *(uint4*)&As[row + 32][c4] = u;
        u.x = f2tf32(wv0.x); u.y = f2tf32(wv0.y); u.z = f2tf32(wv0.z); u.w = f2tf32(wv0.w);
        *(uint4*)&Bs[row][c4] = u;
        u.x = f2tf32(wv1.x); u.y = f2tf32(wv1.y); u.z = f2tf32(wv1.z); u.w = f2tf32(wv1.w);
        *(uint4*)&Bs[row + 32][c4] = u;
        __syncthreads();

        if (c + 1 < nC) {
            int k0 = (c + 1) * 32;
            xv0 = *(const float4*)(ap0 + k0);
            xv1 = *(const float4*)(ap1 + k0);
            wv0 = *(const float4*)(bp0 + k0);
            wv1 = *(const float4*)(bp1 + k0);
        }
#pragma unroll
        for (int ks = 0; ks < 4; ks++) {
            int kk = ks * 8;
            uint32_t a0 = As[m0 + (lane >> 2)][kk + (lane & 3)];
            uint32_t a1 = As[m0 + (lane >> 2) + 8][kk + (lane & 3)];
            uint32_t a2 = As[m0 + (lane >> 2)][kk + (lane & 3) + 4];
            uint32_t a3 = As[m0 + (lane >> 2) + 8][kk + (lane & 3) + 4];
#pragma unroll
            for (int nt = 0; nt < 4; nt++) {
                uint32_t b0 = Bs[n0 + nt * 8 + (lane >> 2)][kk + (lane & 3)];
                uint32_t b1 = Bs[n0 + nt * 8 + (lane >> 2)][kk + (lane & 3) + 4];
                mma_tf32(acc[nt][0], acc[nt][1], acc[nt][2], acc[nt][3],
                         a0, a1, a2, a3, b0, b1);
            }
        }
        __syncthreads();
    }

#pragma unroll
    for (int nt = 0; nt < 4; nt++) {
        int r = m0 + (lane >> 2);
        int cc = nblk * 64 + n0 + nt * 8 + (lane & 3) * 2;
        float bz0 = bias[cc], bz1 = bias[cc + 1];
        *(uint32_t*)&g_enc16[r * Hq + cc] =
            h2_as_u32(__floats2half2_rn(acc[nt][0] + bz0, acc[nt][1] + bz1));
        *(uint32_t*)&g_enc16[(r + 8) * Hq + cc] =
            h2_as_u32(__floats2half2_rn(acc[nt][2] + bz0, acc[nt][3] + bz1));
    }
}

// ============ persistent 4-group dataflow LSTM + logits ============
// grp0 [0,32):  h0(s)           grp1 [32,64): h1(s) = hh-GEMM + pih + epi
// grp2 [64,96): pih(s)          grp3 [96,128): logits(s), N=32 cols
__global__ __launch_bounds__(256, 1)
void lstm_fp16_kernel(const float* __restrict__ bih0, const float* __restrict__ bhh0,
                      const float* __restrict__ bih1, const float* __restrict__ bhh1,
                      const float* __restrict__ b_out,
                      const int* __restrict__ text,
                      float* __restrict__ out) {
    extern __shared__ char smem[];
    float* GSp = (float*)(smem + SM_GSOFF);
    const uint32_t sbase = s2u(smem);

    const int tid = threadIdx.x;
    const int lane = tid & 31, warp = tid >> 5;
    const int gid = lane >> 2, tig = lane & 3;
    const int bid = blockIdx.x;
    const int group = bid >> 5;
    const int blk = bid & 31;
    const int j0 = blk * 32;

    const char* wslice = (group < 3)
        ? (const char*)(g_Wpk + ((size_t)(group * 32 + blk)) * 131072)
        : (const char*)(g_Wout16 + (size_t)j0 * Hq);
    const char* wih0slice = (const char*)(g_Wpk + ((size_t)(3 * 32 + blk)) * 131072);
    const float* b_ih = (group == 0) ? bih0 : bih1;
    const float* b_hh = (group == 0) ? bhh0 : bhh1;
    float bsi = 0.f, bsf = 0.f, bsg = 0.f, bso = 0.f;
    if (group < 2) {
        int j = j0 + lane;
        bsi = b_ih[j] + b_hh[j];
        bsf = b_ih[Hq + j] + b_hh[Hq + j];
        bsg = b_ih[2 * Hq + j] + b_hh[2 * Hq + j];
        bso = b_ih[3 * Hq + j] + b_hh[3 * Hq + j];
    }

    // loader assignments
    const int xrow = tid >> 3;         // 0..31 (+32 for second X row batch)
    const int xu = tid & 7;            // uint4 slot within 64-half row-chunk
    // warp tiles
    const int mw = (warp & 1) * 32;          // batch half
    const int nw = (warp >> 1) * 32;         // main: 32 gate-rows
    const int nwD = (warp >> 1) * 8;         // grp3: 8 logit cols

    float creg[8];
#pragma unroll
    for (int q = 0; q < 8; q++) creg[q] = 0.f;

    for (int s = 0; s <= 126; s++) {
        // ---- dataflow waits ----
        if (tid == 0) {
            if (group == 0) {
                if (s >= 1) waitflag(&g_fh0[s - 1], 32);
            } else if (group == 2) {
                waitflag(&g_fh0[s], 32);
                if (s >= 2) waitflag(&g_fh1[s - 2], 32);   // WAR on pih parity
            } else if (group == 1) {
                waitflag(&g_fpih[s], 32);
                if (s >= 1) waitflag(&g_fh1[s - 1], 32);
            } else {
                waitflag(&g_fh1[s], 32);
            }
        }
        __syncthreads();

        const char* Xsrc;
        const char* wsl = wslice;
        bool doGemm = true;
        if (group == 0) {
            if (s == 0) { Xsrc = (const char*)g_enc16; wsl = wih0slice; }
            else Xsrc = (const char*)(g_h0h + (size_t)(s - 1) * Bq * Hq);
        } else if (group == 1) {
            doGemm = (s >= 1);
            Xsrc = doGemm ? (const char*)(g_outs16 + (size_t)(s - 1) * Bq * Hq) : nullptr;
        } else if (group == 2) {
            Xsrc = (const char*)(g_h0h + (size_t)s * Bq * Hq);
        } else {
            Xsrc = (const char*)(g_outs16 + (size_t)s * Bq * Hq);
        }

        if (group == 3) {
            // ---- logits: D[64 x 32] = outs16[s] @ Wout[j0:j0+32]^T ----
            float acc[2][4] = {};
            uint4 xv[2], wv;
            auto LDGD = [&](int c) {
                int cb = c * 128;
#pragma unroll
                for (int i = 0; i < 2; i++)
                    xv[i] = __ldcg((const uint4*)(Xsrc + (size_t)(xrow + 32 * i) * 2048 + cb + xu * 16));
                wv = *(const uint4*)(wsl + (size_t)xrow * 2048 + cb + xu * 16);
            };
            auto STSD = [&](int b) {
#pragma unroll
                for (int i = 0; i < 2; i++)
                    *(uint4*)(smem + b * 9216 + (xrow + 32 * i) * 144 + xu * 16) = xv[i];
                *(uint4*)(smem + SM_WOFF + b * 18432 + xrow * 144 + xu * 16) = wv;
            };
            LDGD(0);
            STSD(0);
            __syncthreads();
            for (int c = 0; c < 16; c++) {
                const int buf = c & 1;
                if (c + 1 < 16) LDGD(c + 1);
                const uint32_t xb = sbase + buf * 9216;
                const uint32_t wb = sbase + SM_WOFF + buf * 18432;
                uint32_t hacc[2][2] = {};
#pragma unroll
                for (int ks = 0; ks < 4; ks++) {
                    int kh = ks * 16;
                    uint32_t a[2][4], b0, b1;
#pragma unroll
                    for (int ms = 0; ms < 2; ms++) {
                        uint32_t ra = xb + (mw + ms * 16 + (lane & 15)) * 144
                                    + (kh + ((lane >> 4) << 3)) * 2;
                        ldsm_x4(a[ms][0], a[ms][1], a[ms][2], a[ms][3], ra);
                    }
                    uint32_t rb = wb + (nwD + (lane & 7)) * 144
                                + (kh + (((lane >> 3) & 1) << 3)) * 2;
                    ldsm_x2(b0, b1, rb);
#pragma unroll
                    for (int ms = 0; ms < 2; ms++)
                        mma16816h(hacc[ms][0], hacc[ms][1],
                                  a[ms][0], a[ms][1], a[ms][2], a[ms][3], b0, b1);
                }
#pragma unroll
                for (int ms = 0; ms < 2; ms++)
                    promo4(acc[ms], hacc[ms][0], hacc[ms][1]);
                if (c + 1 < 16) STSD(buf ^ 1);
                __syncthreads();
            }
            int n = j0 + nwD + tig * 2;
            float bz0 = b_out[n], bz1 = b_out[n + 1];
#pragma unroll
            for (int ms = 0; ms < 2; ms++) {
                int m = mw + ms * 16 + gid;
                __stcs((float2*)&out[((size_t)m * Lq + s) * Hq + n],
                       make_float2(acc[ms][0] + bz0, acc[ms][1] + bz1));
                __stcs((float2*)&out[((size_t)(m + 8) * Lq + s) * Hq + n],
                       make_float2(acc[ms][2] + bz0, acc[ms][3] + bz1));
            }
            __syncthreads();
            continue;
        }

        float acc[2][4][4] = {};
        if (doGemm) {
            uint4 xv[2], wv[4];
            auto LDGC = [&](int c) {
                int cb = c * 128;
#pragma unroll
                for (int i = 0; i < 2; i++)
                    xv[i] = __ldcg((const uint4*)(Xsrc + (size_t)(xrow + 32 * i) * 2048 + cb + xu * 16));
#pragma unroll
                for (int i = 0; i < 4; i++)
                    wv[i] = *(const uint4*)(wsl + (size_t)(xrow + 32 * i) * 2048 + cb + xu * 16);
            };
            auto STSC = [&](int b) {
#pragma unroll
                for (int i = 0; i < 2; i++)
                    *(uint4*)(smem + b * 9216 + (xrow + 32 * i) * 144 + xu * 16) = xv[i];
#pragma unroll
                for (int i = 0; i < 4; i++)
                    *(uint4*)(smem + SM_WOFF + b * 18432 + (xrow + 32 * i) * 144 + xu * 16) = wv[i];
            };

            LDGC(0);
            STSC(0);
            __syncthreads();
            for (int c = 0; c < 16; c++) {
                const int buf = c & 1;
                if (c + 1 < 16) LDGC(c + 1);
                const uint32_t xb = sbase + buf * 9216;
                const uint32_t wb = sbase + SM_WOFF + buf * 18432;
                uint32_t hacc[2][4][2] = {};
#pragma unroll
                for (int ks = 0; ks < 4; ks++) {
                    int kh = ks * 16;
                    uint32_t a[2][4], b[2][4];
#pragma unroll
                    for (int ms = 0; ms < 2; ms++) {
                        uint32_t ra = xb + (mw + ms * 16 + (lane & 15)) * 144
                                    + (kh + ((lane >> 4) << 3)) * 2;
                        ldsm_x4(a[ms][0], a[ms][1], a[ms][2], a[ms][3], ra);
                    }
#pragma unroll
                    for (int nt2 = 0; nt2 < 2; nt2++) {
                        uint32_t rb = wb + (nw + nt2 * 16 + (lane & 7) + ((lane >> 4) << 3)) * 144
                                    + (kh + (((lane >> 3) & 1) << 3)) * 2;
                        ldsm_x4(b[nt2][0], b[nt2][1], b[nt2][2], b[nt2][3], rb);
                    }
#pragma unroll
                    for (int nt = 0; nt < 4; nt++) {
                        uint32_t b0 = b[nt >> 1][(nt & 1) * 2];
                        uint32_t b1 = b[nt >> 1][(nt & 1) * 2 + 1];
#pragma unroll
                        for (int ms = 0; ms < 2; ms++)
                            mma16816h(hacc[ms][nt][0], hacc[ms][nt][1],
                                      a[ms][0], a[ms][1], a[ms][2], a[ms][3], b0, b1);
                    }
                }
#pragma unroll
                for (int ms = 0; ms < 2; ms++)
#pragma unroll
                    for (int nt = 0; nt < 4; nt++)
                        promo4(acc[ms][nt], hacc[ms][nt][0], hacc[ms][nt][1]);
                if (c + 1 < 16) STSC(buf ^ 1);
                __syncthreads();
            }
        }

        // stage gates into GS[m][r]  (m batch, r = gate*32 + unit)
#pragma unroll
        for (int ms = 0; ms < 2; ms++)
#pragma unroll
            for (int nt = 0; nt < 4; nt++)
#pragma unroll
                for (int hh = 0; hh < 2; hh++) {
                    int m = mw + ms * 16 + gid + hh * 8;
                    int r = nw + nt * 8 + tig * 2;
                    *(float2*)&GSp[m * 130 + r] =
                        make_float2(acc[ms][nt][hh * 2], acc[ms][nt][hh * 2 + 1]);
                }
        __syncthreads();

        if (group == 2) {
            __half* pout = g_pih[s & 1];
            for (int idx = tid; idx < 8192; idx += 256) {
                int m = idx >> 7, gl = idx & 127;
                int gn = (gl >> 5) * Hq + j0 + (gl & 31);
                pout[(size_t)m * NG + gn] = __float2half(GSp[m * 130 + gl]);
            }
        } else {
            const int j = j0 + lane;
            __half* hout = (group == 0) ? (g_h0h + (size_t)s * Bq * Hq)
                                        : (g_outs16 + (size_t)s * Bq * Hq);
            const __half* pin = (group == 1) ? g_pih[s & 1] : nullptr;
#pragma unroll
            for (int q = 0; q < 8; q++) {
                int m = warp + 8 * q;
                float vi = GSp[m * 130 + lane] + bsi;
                float vf = GSp[m * 130 + 32 + lane] + bsf;
                float vg = GSp[m * 130 + 64 + lane] + bsg;
                float vo = GSp[m * 130 + 96 + lane] + bso;
                if (group == 0) {
                    if (s > 0) {
                        int ix = text[m * SEQLEN + s];
                        const float* wt = g_WT + (size_t)ix * NG;
                        vi += wt[j]; vf += wt[Hq + j];
                        vg += wt[2 * Hq + j]; vo += wt[3 * Hq + j];
                    }
                } else {
                    const __half* pm = pin + (size_t)m * NG;
                    vi += __half2float(pm[j]);
                    vf += __half2float(pm[Hq + j]);
                    vg += __half2float(pm[2 * Hq + j]);
                    vo += __half2float(pm[3 * Hq + j]);
                }
                float ig = sigf(vi), fg = sigf(vf), gg = tanhf(vg), og = sigf(vo);
                float cn = fg * creg[q] + ig * gg;
                creg[q] = cn;
                hout[m * Hq + j] = __float2half(og * tanhf(cn));
            }
        }
        __syncthreads();

        // ---- publish completion flag ----
        if (tid == 0) {
            __threadfence();
            if (group == 0) atomicAdd(&g_fh0[s], 1);
            else if (group == 2) atomicAdd(&g_fpih[s], 1);
            else atomicAdd(&g_fh1[s], 1);
        }
    }
}

// -------- host launch --------
extern "C" void kernel_launch(void* const* d_in, const int* in_sizes, int n_in,
                              void* d_out, int out_size) {
    const float* audio  = (const float*)d_in[0];
    const int*   text   = (const int*)d_in[1];
    const float* W_proj = (const float*)d_in[2];
    const float* b_proj = (const float*)d_in[3];
    const float* W_ih0  = (const float*)d_in[4];
    const float* W_hh0  = (const float*)d_in[5];
    const float* b_ih0  = (const float*)d_in[6];
    const float* b_hh0  = (const float*)d_in[7];
    const float* W_ih1  = (const float*)d_in[8];
    const float* W_hh1  = (const float*)d_in[9];
    const float* b_ih1  = (const float*)d_in[10];
    const float* b_hh1  = (const float*)d_in[11];
    const float* W_out  = (const float*)d_in[12];
    const float* b_out  = (const float*)d_in[13];
    float* out = (float*)d_out;

    cudaFuncSetAttribute(lstm_fp16_kernel,
                         cudaFuncAttributeMaxDynamicSharedMemorySize, SMEM_BYTES);

    // fused prologue: reset | pool | pack W | pack Wout | transpose
    prep_kernel<<<5826, 256>>>(audio, W_hh0, W_hh1, W_ih1, W_ih0, W_out);
    // enc = pooled @ W_proj^T + b_proj -> fp16
    gemm_enc_kernel<<<16, 256>>>(W_proj, b_proj, DIN);

    lstm_fp16_kernel<<<NPB, 256, SMEM_BYTES>>>(b_ih0, b_hh0, b_ih1, b_hh1,
                                               b_out, text, out);
}

// round 17
// speedup vs baseline: 1.6920x; 1.0106x over previous
#include <cuda_runtime.h>
#include <cuda_fp16.h>
#include <cstdint>

#define Bq 64
#define Hq 1024
#define NG 4096
#define DIN 768
#define TAUD 500
#define Lq 127
#define SEQLEN 128
#define NPB 128       // 4 groups x 32 blocks

// ---- dynamic smem layout (bytes) ----
#define SM_WOFF 18432
#define SM_GSOFF 55296
#define SMEM_BYTES 88576

// -------- scratch --------
__device__ float g_pooled[Bq * DIN];
__device__ __half g_enc16[Bq * Hq];
__device__ float g_WT[Hq * NG];                    // Wih0^T: [char][gate-row]
__device__ __half g_Wpk[4u * 32u * 128u * 1024u];  // Whh0, Whh1, Wih1, Wih0
__device__ __half g_Wout16[Hq * Hq];               // fp16 W_out [n][k]
__device__ __half g_h0h[(size_t)Lq * Bq * Hq];     // h0 full history
__device__ __half g_outs16[(size_t)Lq * Bq * Hq];  // h1 history == outputs
__device__ __half g_pih[2][Bq * NG];               // layer1 partial ih gates (fp16)
__device__ int g_fh0[Lq];
__device__ int g_fpih[Lq];
__device__ int g_fh1[Lq];

__device__ __forceinline__ float sigf(float x) { return 1.0f / (1.0f + __expf(-x)); }

__device__ __forceinline__ uint32_t h2_as_u32(__half2 h) {
    return *reinterpret_cast<uint32_t*>(&h);
}

__device__ __forceinline__ uint32_t s2u(const void* p) {
    uint32_t a;
    asm("{ .reg .u64 t; cvta.to.shared.u64 t, %1; cvt.u32.u64 %0, t; }" : "=r"(a) : "l"(p));
    return a;
}

__device__ __forceinline__ uint32_t f2tf32(float f) {
    uint32_t u;
    asm("cvt.rna.tf32.f32 %0, %1;" : "=r"(u) : "f"(f));
    return u;
}

__device__ __forceinline__ void ldsm_x4(uint32_t& r0, uint32_t& r1, uint32_t& r2, uint32_t& r3,
                                        uint32_t addr) {
    asm volatile("ldmatrix.sync.aligned.m8n8.x4.shared.b16 {%0,%1,%2,%3}, [%4];"
                 : "=r"(r0), "=r"(r1), "=r"(r2), "=r"(r3) : "r"(addr));
}
__device__ __forceinline__ void ldsm_x2(uint32_t& r0, uint32_t& r1, uint32_t addr) {
    asm volatile("ldmatrix.sync.aligned.m8n8.x2.shared.b16 {%0,%1}, [%2];"
                 : "=r"(r0), "=r"(r1) : "r"(addr));
}

// fp16 mma with fp16 accumulators (packed half2 x2)
__device__ __forceinline__ void mma16816h(uint32_t& d0, uint32_t& d1,
                                          uint32_t a0, uint32_t a1, uint32_t a2, uint32_t a3,
                                          uint32_t b0, uint32_t b1) {
    asm volatile("mma.sync.aligned.m16n8k16.row.col.f16.f16.f16.f16 "
                 "{%0,%1}, {%2,%3,%4,%5}, {%6,%7}, {%0,%1};"
                 : "+r"(d0), "+r"(d1)
                 : "r"(a0), "r"(a1), "r"(a2), "r"(a3), "r"(b0), "r"(b1));
}

// promote packed f16 pair into 4 f32 accumulators
__device__ __forceinline__ void promo4(float* a4, uint32_t h0, uint32_t h1) {
    float2 lo = __half22float2(*reinterpret_cast<__half2*>(&h0));
    float2 hi = __half22float2(*reinterpret_cast<__half2*>(&h1));
    a4[0] += lo.x; a4[1] += lo.y; a4[2] += hi.x; a4[3] += hi.y;
}

// tf32 SIMT mma (prologue GEMM)
__device__ __forceinline__ void mma_tf32(float& c0, float& c1, float& c2, float& c3,
                                         uint32_t a0, uint32_t a1, uint32_t a2, uint32_t a3,
                                         uint32_t b0, uint32_t b1) {
    asm volatile("mma.sync.aligned.m16n8k8.row.col.f32.tf32.tf32.f32 "
                 "{%0,%1,%2,%3}, {%4,%5,%6,%7}, {%8,%9}, {%0,%1,%2,%3};"
                 : "+f"(c0), "+f"(c1), "+f"(c2), "+f"(c3)
                 : "r"(a0), "r"(a1), "r"(a2), "r"(a3), "r"(b0), "r"(b1));
}

__device__ __forceinline__ void waitflag(const int* f, int need) {
    int v;
    do {
        asm volatile("ld.acquire.gpu.s32 %0, [%1];" : "=r"(v) : "l"(f));
    } while (v < need);
}

// ============ fused prologue: reset | pool | pack W | pack Wout | transpose ============
// block ranges: [0,2) reset flags | [2,194) pool | [194,706) pack_w16 |
//               [706,1730) pack_wout | [1730,5826) transpose (4096 tiles)
__global__ __launch_bounds__(256)
void prep_kernel(const float* __restrict__ audio,
                 const float* __restrict__ W0, const float* __restrict__ W1,
                 const float* __restrict__ W2, const float* __restrict__ W3,
                 const float* __restrict__ Wout) {
    const int b = blockIdx.x;
    const int tid = threadIdx.x;

    if (b < 2) {                      // ---- reset flags ----
        int i = b * 256 + tid;
        if (i < Lq) { g_fh0[i] = 0; g_fpih[i] = 0; g_fh1[i] = 0; }
        return;
    }
    if (b < 194) {                    // ---- mean-pool audio (4-way MLP) ----
        int i = (b - 2) * 256 + tid;  // B*DIN = 49152
        int bb = i / DIN, d = i % DIN;
        const float* p = audio + (size_t)bb * TAUD * DIN + d;
        float s0 = 0.f, s1 = 0.f, s2 = 0.f, s3 = 0.f;
#pragma unroll 5
        for (int t = 0; t < TAUD; t += 4) {
            s0 += __ldcs(p + (size_t)t * DIN);
            s1 += __ldcs(p + (size_t)(t + 1) * DIN);
            s2 += __ldcs(p + (size_t)(t + 2) * DIN);
            s3 += __ldcs(p + (size_t)(t + 3) * DIN);
        }
        g_pooled[i] = ((s0 + s1) + (s2 + s3)) * (1.0f / TAUD);
        return;
    }
    if (b < 706) {                    // ---- pack LSTM weights to fp16 slices ----
        int id = b - 194;             // 0..511
        int grp = id >> 7;
        int rem = id & 127;
        int blk = rem >> 2;
        int qtr = rem & 3;
        const float* W = (grp == 0) ? W0 : (grp == 1 ? W1 : (grp == 2 ? W2 : W3));
        int j0 = blk * 32;
        __half* dst = g_Wpk + ((size_t)(grp * 32 + blk)) * 131072;
        int f4e = (qtr + 1) * 8192;
        for (int f4 = qtr * 8192 + tid; f4 < f4e; f4 += 256) {
            int r = f4 >> 8;
            int c = (f4 & 255) * 4;
            int grow = (r >> 5) * Hq + j0 + (r & 31);
            float4 v = *(const float4*)(W + (size_t)grow * Hq + c);
            uint2 o;
            o.x = h2_as_u32(__floats2half2_rn(v.x, v.y));
            o.y = h2_as_u32(__floats2half2_rn(v.z, v.w));
            *(uint2*)(dst + (size_t)r * 1024 + c) = o;
        }
        return;
    }
    if (b < 1730) {                   // ---- pack W_out to fp16 ----
        int i = (b - 706) * 256 + tid;
        float4 v = *(const float4*)(Wout + (size_t)i * 4);
        uint2 o;
        o.x = h2_as_u32(__floats2half2_rn(v.x, v.y));
        o.y = h2_as_u32(__floats2half2_rn(v.z, v.w));
        *(uint2*)(g_Wout16 + (size_t)i * 4) = o;
        return;
    }
    {                                 // ---- transpose Wih0 -> WT[char][gate-row] ----
        __shared__ float tile[32][33];
        int t32 = b - 1730;           // 0..4095
        int bx = t32 & 31, by = t32 >> 5;
        int tx = tid & 31, ty0 = tid >> 5;
#pragma unroll
        for (int q = 0; q < 4; q++) {
            int ty = ty0 + q * 8;
            tile[ty][tx] = W3[(size_t)(by * 32 + ty) * Hq + bx * 32 + tx];
        }
        __syncthreads();
#pragma unroll
        for (int q = 0; q < 4; q++) {
            int ty = ty0 + q * 8;
            g_WT[(size_t)(bx * 32 + ty) * NG + by * 32 + tx] = tile[tx][ty];
        }
        return;
    }
}

// ============ SIMT tf32 GEMM: enc = pooled @ W_proj^T + b -> fp16 [m][k] ============
__global__ __launch_bounds__(256, 2)
void gemm_enc_kernel(const float* __restrict__ Bw,
                     const float* __restrict__ bias, int K) {
    __shared__ uint32_t As[64][36];
    __shared__ uint32_t Bs[64][36];
    const float* A = g_pooled;

    int tid = threadIdx.x;
    int lane = tid & 31, warp = tid >> 5;
    int nblk = blockIdx.x;
    int m0 = (warp & 3) * 16;
    int n0 = (warp >> 2) * 32;
    float acc[4][4] = {};
    int row = tid >> 3;
    int c4 = (tid & 7) * 4;

    const float* ap0 = A + (size_t)row * K + c4;
    const float* ap1 = A + (size_t)(row + 32) * K + c4;
    const float* bp0 = Bw + (size_t)(nblk * 64 + row) * K + c4;
    const float* bp1 = Bw + (size_t)(nblk * 64 + row + 32) * K + c4;

    int nC = K / 32;
    float4 xv0 = *(const float4*)ap0;
    float4 xv1 = *(const float4*)ap1;
    float4 wv0 = *(const float4*)bp0;
    float4 wv1 = *(const float4*)bp1;

    for (int c = 0; c < nC; c++) {
        uint4 u;
        u.x = f2tf32(xv0.x); u.y = f2tf32(xv0.y); u.z = f2tf32(xv0.z); u.w = f2tf32(xv0.w);
        *(uint4*)&As[row][c4] = u;
        u.x = f2tf32(xv1.x); u.y = f2tf32(xv1.y); u.z = f2tf32(xv1.z); u.w = f2tf32(xv1.w);
        *(uint4*)&As[row + 32][c4] = u;
        u.x = f2tf32(wv0.x); u.y = f2tf32(wv0.y); u.z = f2tf32(wv0.z); u.w = f2tf32(wv0.w);
        *(uint4*)&Bs[row][c4] = u;
        u.x = f2tf32(wv1.x); u.y = f2tf32(wv1.y); u.z = f2tf32(wv1.z); u.w = f2tf32(wv1.w);
        *(uint4*)&Bs[row + 32][c4] = u;
        __syncthreads();

        if (c + 1 < nC) {
            int k0 = (c + 1) * 32;
            xv0 = *(const float4*)(ap0 + k0);
            xv1 = *(const float4*)(ap1 + k0);
            wv0 = *(const float4*)(bp0 + k0);
            wv1 = *(const float4*)(bp1 + k0);
        }
#pragma unroll
        for (int ks = 0; ks < 4; ks++) {
            int kk = ks * 8;
            uint32_t a0 = As[m0 + (lane >> 2)][kk + (lane & 3)];
            uint32_t a1 = As[m0 + (lane >> 2) + 8][kk + (lane & 3)];
            uint32_t a2 = As[m0 + (lane >> 2)][kk + (lane & 3) + 4];
            uint32_t a3 = As[m0 + (lane >> 2) + 8][kk + (lane & 3) + 4];
#pragma unroll
            for (int nt = 0; nt < 4; nt++) {
                uint32_t b0 = Bs[n0 + nt * 8 + (lane >> 2)][kk + (lane & 3)];
                uint32_t b1 = Bs[n0 + nt * 8 + (lane >> 2)][kk + (lane & 3) + 4];
                mma_tf32(acc[nt][0], acc[nt][1], acc[nt][2], acc[nt][3],
                         a0, a1, a2, a3, b0, b1);
            }
        }
        __syncthreads();
    }

#pragma unroll
    for (int nt = 0; nt < 4; nt++) {
        int r = m0 + (lane >> 2);
        int cc = nblk * 64 + n0 + nt * 8 + (lane & 3) * 2;
        float bz0 = bias[cc], bz1 = bias[cc + 1];
        *(uint32_t*)&g_enc16[r * Hq + cc] =
            h2_as_u32(__floats2half2_rn(acc[nt][0] + bz0, acc[nt][1] + bz1));
        *(uint32_t*)&g_enc16[(r + 8) * Hq + cc] =
            h2_as_u32(__floats2half2_rn(acc[nt][2] + bz0, acc[nt][3] + bz1));
    }
}

// ============ persistent 4-group dataflow LSTM + logits ============
// grp0 [0,32):  h0(s)           grp1 [32,64): h1(s) = hh-GEMM + pih + epi
// grp2 [64,96): pih(s)          grp3 [96,128): logits(s), N=32 cols
__global__ __launch_bounds__(256, 1)
void lstm_fp16_kernel(const float* __restrict__ bih0, const float* __restrict__ bhh0,
                      const float* __restrict__ bih1, const float* __restrict__ bhh1,
                      const float* __restrict__ b_out,
                      const int* __restrict__ text,
                      float* __restrict__ out) {
    extern __shared__ char smem[];
    float* GSp = (float*)(smem + SM_GSOFF);
    const uint32_t sbase = s2u(smem);

    const int tid = threadIdx.x;
    const int lane = tid & 31, warp = tid >> 5;
    const int gid = lane >> 2, tig = lane & 3;
    const int bid = blockIdx.x;
    const int group = bid >> 5;
    const int blk = bid & 31;
    const int j0 = blk * 32;

    const char* wslice = (group < 3)
        ? (const char*)(g_Wpk + ((size_t)(group * 32 + blk)) * 131072)
        : (const char*)(g_Wout16 + (size_t)j0 * Hq);
    const char* wih0slice = (const char*)(g_Wpk + ((size_t)(3 * 32 + blk)) * 131072);
    const float* b_ih = (group == 0) ? bih0 : bih1;
    const float* b_hh = (group == 0) ? bhh0 : bhh1;
    float bsi = 0.f, bsf = 0.f, bsg = 0.f, bso = 0.f;
    if (group < 2) {
        int j = j0 + lane;
        bsi = b_ih[j] + b_hh[j];
        bsf = b_ih[Hq + j] + b_hh[Hq + j];
        bsg = b_ih[2 * Hq + j] + b_hh[2 * Hq + j];
        bso = b_ih[3 * Hq + j] + b_hh[3 * Hq + j];
    }

    // loader assignments
    const int xrow = tid >> 3;         // 0..31 (+32 for second X row batch)
    const int xu = tid & 7;            // uint4 slot within 64-half row-chunk
    // warp tiles
    const int mw = (warp & 1) * 32;          // batch half
    const int nw = (warp >> 1) * 32;         // main: 32 gate-rows
    const int nwD = (warp >> 1) * 8;         // grp3: 8 logit cols

    float creg[8];
#pragma unroll
    for (int q = 0; q < 8; q++) creg[q] = 0.f;

    for (int s = 0; s <= 126; s++) {
        // ---- dataflow waits ----
        if (tid == 0) {
            if (group == 0) {
                if (s >= 1) waitflag(&g_fh0[s - 1], 32);
            } else if (group == 2) {
                waitflag(&g_fh0[s], 32);
                if (s >= 2) waitflag(&g_fh1[s - 2], 32);   // WAR on pih parity
            } else if (group == 1) {
                waitflag(&g_fpih[s], 32);
                if (s >= 1) waitflag(&g_fh1[s - 1], 32);
            } else {
                waitflag(&g_fh1[s], 32);
            }
        }
        __syncthreads();

        const char* Xsrc;
        const char* wsl = wslice;
        bool doGemm = true;
        if (group == 0) {
            if (s == 0) { Xsrc = (const char*)g_enc16; wsl = wih0slice; }
            else Xsrc = (const char*)(g_h0h + (size_t)(s - 1) * Bq * Hq);
        } else if (group == 1) {
            doGemm = (s >= 1);
            Xsrc = doGemm ? (const char*)(g_outs16 + (size_t)(s - 1) * Bq * Hq) : nullptr;
        } else if (group == 2) {
            Xsrc = (const char*)(g_h0h + (size_t)s * Bq * Hq);
        } else {
            Xsrc = (const char*)(g_outs16 + (size_t)s * Bq * Hq);
        }

        if (group == 3) {
            // ---- logits: D[64 x 32] = outs16[s] @ Wout[j0:j0+32]^T ----
            float acc[2][4] = {};
            uint4 xv[2], wv;
            auto LDGD = [&](int c) {
                int cb = c * 128;
#pragma unroll
                for (int i = 0; i < 2; i++)
                    xv[i] = __ldcg((const uint4*)(Xsrc + (size_t)(xrow + 32 * i) * 2048 + cb + xu * 16));
                wv = *(const uint4*)(wsl + (size_t)xrow * 2048 + cb + xu * 16);
            };
            auto STSD = [&](int b) {
#pragma unroll
                for (int i = 0; i < 2; i++)
                    *(uint4*)(smem + b * 9216 + (xrow + 32 * i) * 144 + xu * 16) = xv[i];
                *(uint4*)(smem + SM_WOFF + b * 18432 + xrow * 144 + xu * 16) = wv;
            };
            LDGD(0);
            STSD(0);
            __syncthreads();
            for (int c = 0; c < 16; c++) {
                const int buf = c & 1;
                if (c + 1 < 16) LDGD(c + 1);
                const uint32_t xb = sbase + buf * 9216;
                const uint32_t wb = sbase + SM_WOFF + buf * 18432;
                uint32_t hacc[2][2] = {};
#pragma unroll
                for (int ks = 0; ks < 4; ks++) {
                    int kh = ks * 16;
                    uint32_t a[2][4], b0, b1;
#pragma unroll
                    for (int ms = 0; ms < 2; ms++) {
                        uint32_t ra = xb + (mw + ms * 16 + (lane & 15)) * 144
                                    + (kh + ((lane >> 4) << 3)) * 2;
                        ldsm_x4(a[ms][0], a[ms][1], a[ms][2], a[ms][3], ra);
                    }
                    uint32_t rb = wb + (nwD + (lane & 7)) * 144
                                + (kh + (((lane >> 3) & 1) << 3)) * 2;
                    ldsm_x2(b0, b1, rb);
#pragma unroll
                    for (int ms = 0; ms < 2; ms++)
                        mma16816h(hacc[ms][0], hacc[ms][1],
                                  a[ms][0], a[ms][1], a[ms][2], a[ms][3], b0, b1);
                }
#pragma unroll
                for (int ms = 0; ms < 2; ms++)
                    promo4(acc[ms], hacc[ms][0], hacc[ms][1]);
                if (c + 1 < 16) STSD(buf ^ 1);
                __syncthreads();
            }
            int n = j0 + nwD + tig * 2;
            float bz0 = b_out[n], bz1 = b_out[n + 1];
#pragma unroll
            for (int ms = 0; ms < 2; ms++) {
                int m = mw + ms * 16 + gid;
                __stcs((float2*)&out[((size_t)m * Lq + s) * Hq + n],
                       make_float2(acc[ms][0] + bz0, acc[ms][1] + bz1));
                __stcs((float2*)&out[((size_t)(m + 8) * Lq + s) * Hq + n],
                       make_float2(acc[ms][2] + bz0, acc[ms][3] + bz1));
            }
            __syncthreads();
            continue;
        }

        float acc[2][4][4] = {};
        if (doGemm) {
            uint4 xv[2], wv[4];
            auto LDGC = [&](int c) {
                int cb = c * 128;
#pragma unroll
                for (int i = 0; i < 2; i++)
                    xv[i] = __ldcg((const uint4*)(Xsrc + (size_t)(xrow + 32 * i) * 2048 + cb + xu * 16));
#pragma unroll
                for (int i = 0; i < 4; i++)
                    wv[i] = *(const uint4*)(wsl + (size_t)(xrow + 32 * i) * 2048 + cb + xu * 16);
            };
            auto STSC = [&](int b) {
#pragma unroll
                for (int i = 0; i < 2; i++)
                    *(uint4*)(smem + b * 9216 + (xrow + 32 * i) * 144 + xu * 16) = xv[i];
#pragma unroll
                for (int i = 0; i < 4; i++)
                    *(uint4*)(smem + SM_WOFF + b * 18432 + (xrow + 32 * i) * 144 + xu * 16) = wv[i];
            };

            LDGC(0);
            STSC(0);
            __syncthreads();
            uint32_t hacc[2][4][2];
            for (int c = 0; c < 16; c++) {
                const int buf = c & 1;
                if (c + 1 < 16) LDGC(c + 1);
                const uint32_t xb = sbase + buf * 9216;
                const uint32_t wb = sbase + SM_WOFF + buf * 18432;
                if ((c & 1) == 0) {
#pragma unroll
                    for (int ms = 0; ms < 2; ms++)
#pragma unroll
                        for (int nt = 0; nt < 4; nt++) {
                            hacc[ms][nt][0] = 0u;
                            hacc[ms][nt][1] = 0u;
                        }
                }
#pragma unroll
                for (int ks = 0; ks < 4; ks++) {
                    int kh = ks * 16;
                    uint32_t a[2][4], b[2][4];
#pragma unroll
                    for (int ms = 0; ms < 2; ms++) {
                        uint32_t ra = xb + (mw + ms * 16 + (lane & 15)) * 144
                                    + (kh + ((lane >> 4) << 3)) * 2;
                        ldsm_x4(a[ms][0], a[ms][1], a[ms][2], a[ms][3], ra);
                    }
#pragma unroll
                    for (int nt2 = 0; nt2 < 2; nt2++) {
                        uint32_t rb = wb + (nw + nt2 * 16 + (lane & 7) + ((lane >> 4) << 3)) * 144
                                    + (kh + (((lane >> 3) & 1) << 3)) * 2;
                        ldsm_x4(b[nt2][0], b[nt2][1], b[nt2][2], b[nt2][3], rb);
                    }
#pragma unroll
                    for (int nt = 0; nt < 4; nt++) {
                        uint32_t b0 = b[nt >> 1][(nt & 1) * 2];
                        uint32_t b1 = b[nt >> 1][(nt & 1) * 2 + 1];
#pragma unroll
                        for (int ms = 0; ms < 2; ms++)
                            mma16816h(hacc[ms][nt][0], hacc[ms][nt][1],
                                      a[ms][0], a[ms][1], a[ms][2], a[ms][3], b0, b1);
                    }
                }
                if (c & 1) {
#pragma unroll
                    for (int ms = 0; ms < 2; ms++)
#pragma unroll
                        for (int nt = 0; nt < 4; nt++)
                            promo4(acc[ms][nt], hacc[ms][nt][0], hacc[ms][nt][1]);
                }
                if (c + 1 < 16) STSC(buf ^ 1);
                __syncthreads();
            }
        }

        // stage gates into GS[m][r]  (m batch, r = gate*32 + unit)
#pragma unroll
        for (int ms = 0; ms < 2; ms++)
#pragma unroll
            for (int nt = 0; nt < 4; nt++)
#pragma unroll
                for (int hh = 0; hh < 2; hh++) {
                    int m = mw + ms * 16 + gid + hh * 8;
                    int r = nw + nt * 8 + tig * 2;
                    *(float2*)&GSp[m * 130 + r] =
                        make_float2(acc[ms][nt][hh * 2], acc[ms][nt][hh * 2 + 1]);
                }
        __syncthreads();

        if (group == 2) {
            __half* pout = g_pih[s & 1];
            for (int idx = tid; idx < 8192; idx += 256) {
                int m = idx >> 7, gl = idx & 127;
                int gn = (gl >> 5) * Hq + j0 + (gl & 31);
                pout[(size_t)m * NG + gn] = __float2half(GSp[m * 130 + gl]);
            }
        } else {
            const int j = j0 + lane;
            __half* hout = (group == 0) ? (g_h0h + (size_t)s * Bq * Hq)
                                        : (g_outs16 + (size_t)s * Bq * Hq);
            const __half* pin = (group == 1) ? g_pih[s & 1] : nullptr;
#pragma unroll
            for (int q = 0; q < 8; q++) {
                int m = warp + 8 * q;
                float vi = GSp[m * 130 + lane] + bsi;
                float vf = GSp[m * 130 + 32 + lane] + bsf;
                float vg = GSp[m * 130 + 64 + lane] + bsg;
                float vo = GSp[m * 130 + 96 + lane] + bso;
                if (group == 0) {
                    if (s > 0) {
                        int ix = text[m * SEQLEN + s];
                        const float* wt = g_WT + (size_t)ix * NG;
                        vi += wt[j]; vf += wt[Hq + j];
                        vg += wt[2 * Hq + j]; vo += wt[3 * Hq + j];
                    }
                } else {
                    const __half* pm = pin + (size_t)m * NG;
                    vi += __half2float(pm[j]);
                    vf += __half2float(pm[Hq + j]);
                    vg += __half2float(pm[2 * Hq + j]);
                    vo += __half2float(pm[3 * Hq + j]);
                }
                float ig = sigf(vi), fg = sigf(vf), gg = tanhf(vg), og = sigf(vo);
                float cn = fg * creg[q] + ig * gg;
                creg[q] = cn;
                hout[m * Hq + j] = __float2half(og * tanhf(cn));
            }
        }
        __syncthreads();

        // ---- publish completion flag ----
        if (tid == 0) {
            __threadfence();
            if (group == 0) atomicAdd(&g_fh0[s], 1);
            else if (group == 2) atomicAdd(&g_fpih[s], 1);
            else atomicAdd(&g_fh1[s], 1);
        }
    }
}

// -------- host launch --------
extern "C" void kernel_launch(void* const* d_in, const int* in_sizes, int n_in,
                              void* d_out, int out_size) {
    const float* audio  = (const float*)d_in[0];
    const int*   text   = (const int*)d_in[1];
    const float* W_proj = (const float*)d_in[2];
    const float* b_proj = (const float*)d_in[3];
    const float* W_ih0  = (const float*)d_in[4];
    const float* W_hh0  = (const float*)d_in[5];
    const float* b_ih0  = (const float*)d_in[6];
    const float* b_hh0  = (const float*)d_in[7];
    const float* W_ih1  = (const float*)d_in[8];
    const float* W_hh1  = (const float*)d_in[9];
    const float* b_ih1  = (const float*)d_in[10];
    const float* b_hh1  = (const float*)d_in[11];
    const float* W_out  = (const float*)d_in[12];
    const float* b_out  = (const float*)d_in[13];
    float* out = (float*)d_out;

    cudaFuncSetAttribute(lstm_fp16_kernel,
                         cudaFuncAttributeMaxDynamicSharedMemorySize, SMEM_BYTES);

    // fused prologue: reset | pool | pack W | pack Wout | transpose
    prep_kernel<<<5826, 256>>>(audio, W_hh0, W_hh1, W_ih1, W_ih0, W_out);
    // enc = pooled @ W_proj^T + b_proj -> fp16
    gemm_enc_kernel<<<16, 256>>>(W_proj, b_proj, DIN);

    lstm_fp16_kernel<<<NPB, 256, SMEM_BYTES>>>(b_ih0, b_hh0, b_ih1, b_hh1,
                                               b_out, text, out);
}